// round 2
// baseline (speedup 1.0000x reference)
#include <cuda_runtime.h>
#include <math.h>

#define PP 8
#define TT 200
#define FF 512
#define CC 20
#define QQ 1024
#define NM (PP*CC)   // 160 matrices

// ------------------------- device scratch (no allocation allowed) -------------------------
__device__ float g_means[NM*FF];                   // (P,C,F) class means (also output part 2)
__device__ float g_tm[PP*FF];                      // task means
__device__ float g_task[(size_t)PP*FF*FF];         // task covariances
__device__ float g_M[(size_t)NM*FF*FF];            // cov_reg -> Cholesky L (in place)
__device__ float g_W[(size_t)NM*FF*FF];            // W = L^{-1} (strict upper kept zero)
__device__ float g_quad[(size_t)PP*QQ*CC];         // per-phi quadratic forms
__device__ int   g_members[CC*TT];
__device__ int   g_cnt[CC];
__device__ float g_icnts[CC], g_sclS[CC], g_sclT[CC];

// ------------------------- packed f32x2 helpers (FFMA2: 2x fp32 rate) ---------------------
__device__ __forceinline__ unsigned long long pk2(float lo, float hi){
    unsigned long long r;
    asm("mov.b64 %0, {%1,%2};" : "=l"(r) : "f"(lo), "f"(hi));
    return r;
}
__device__ __forceinline__ void up2(unsigned long long v, float &a, float &b){
    asm("mov.b64 {%0,%1}, %2;" : "=f"(a), "=f"(b) : "l"(v));
}
__device__ __forceinline__ void fma2(unsigned long long &d, unsigned long long a, unsigned long long b){
    asm("fma.rn.f32x2 %0, %1, %2, %0;" : "+l"(d) : "l"(a), "l"(b));
}

// ------------------------- setup: label decode, counts, member lists ----------------------
__global__ void setup_k(const int* __restrict__ lab_raw){
    if (threadIdx.x == 0 && blockIdx.x == 0){
        // Detect int32 vs int64 labels using only first 200 int32 words (safe for both).
        // int64 little-endian view: value at even idx, 0 at odd idx.
        bool odd_all_zero = true;
        for (int t = 1; t < 200; t += 2) if (lab_raw[t] != 0) odd_all_zero = false;
        bool even_has_big = false;
        for (int t = 0; t < 200; t += 2) if (lab_raw[t] > 0) even_has_big = true;
        bool is64 = odd_all_zero && even_has_big;

        int cnt[CC];
        #pragma unroll
        for (int c = 0; c < CC; c++) cnt[c] = 0;
        for (int t = 0; t < TT; t++){
            int cc = is64 ? lab_raw[2*t] : lab_raw[t];
            if (cc < 0) cc = 0; if (cc >= CC) cc = CC-1;
            g_members[cc*TT + cnt[cc]] = t;
            cnt[cc]++;
        }
        for (int c = 0; c < CC; c++){
            g_cnt[c] = cnt[c];
            float cs  = fmaxf((float)cnt[c], 1.0f);
            g_icnts[c] = 1.0f / cs;
            float lam = cs / (cs + 1.0f);
            g_sclS[c] = lam / fmaxf((float)cnt[c] - 1.0f, 1.0f);
            g_sclT[c] = 1.0f - lam;
        }
    }
}

// ------------------------- class means -------------------------
__global__ void means_k(const float* __restrict__ sf){
    int pc = blockIdx.x;
    int p = pc / CC, c = pc % CC;
    int n = g_cnt[c];
    float ic = g_icnts[c];
    for (int f = threadIdx.x; f < FF; f += blockDim.x){
        float s = 0.0f;
        for (int m = 0; m < n; m++){
            int t = g_members[c*TT + m];
            s += sf[((size_t)p*TT + t)*FF + f];
        }
        g_means[(size_t)pc*FF + f] = s * ic;
    }
}

// ------------------------- task mean -------------------------
__global__ void tm_k(const float* __restrict__ sf){
    int p = blockIdx.x;
    for (int f = threadIdx.x; f < FF; f += blockDim.x){
        float s = 0.0f;
        for (int t = 0; t < TT; t++) s += sf[((size_t)p*TT + t)*FF + f];
        g_tm[p*FF + f] = s * (1.0f/TT);
    }
}

// ------------------------- task covariance (64x64 tiles) -------------------------
__global__ void taskcov_k(const float* __restrict__ sf){
    int tile = blockIdx.x;          // 0..63
    int p    = blockIdx.y;
    int tf = tile & 7, tg = tile >> 3;
    __shared__ float af[64], ag[64];
    int tid = threadIdx.x, tx = tid & 15, ty = tid >> 4;
    int r0 = ty*4, c0 = tx*4;
    float acc[4][4] = {};
    for (int t = 0; t < TT; t++){
        __syncthreads();
        if (tid < 64)       af[tid]    = sf[((size_t)p*TT+t)*FF + tf*64 + tid]      - g_tm[p*FF + tf*64 + tid];
        else if (tid < 128) ag[tid-64] = sf[((size_t)p*TT+t)*FF + tg*64 + (tid-64)] - g_tm[p*FF + tg*64 + (tid-64)];
        __syncthreads();
        float a[4], b[4];
        #pragma unroll
        for (int i = 0; i < 4; i++) a[i] = af[r0+i];
        #pragma unroll
        for (int j = 0; j < 4; j++) b[j] = ag[c0+j];
        #pragma unroll
        for (int i = 0; i < 4; i++)
            #pragma unroll
            for (int j = 0; j < 4; j++) acc[i][j] += a[i]*b[j];
    }
    const float inv = 1.0f/(TT-1);
    float* dst = g_task + (size_t)p*FF*FF;
    #pragma unroll
    for (int i = 0; i < 4; i++)
        #pragma unroll
        for (int j = 0; j < 4; j++){
            int fr = tf*64 + r0 + i, gc = tg*64 + c0 + j;
            dst[(size_t)fr*FF + gc] = acc[i][j]*inv;
        }
}

// ------------------------- cov_reg = sclS*Scatter + sclT*Task + I -------------------------
__global__ void buildM_k(const float* __restrict__ sf){
    int tile = blockIdx.x;          // 0..63
    int pc   = blockIdx.y;          // 0..159
    int p = pc / CC, c = pc % CC;
    int tf = tile & 7, tg = tile >> 3;
    __shared__ float af[64], ag[64];
    int tid = threadIdx.x, tx = tid & 15, ty = tid >> 4;
    int r0 = ty*4, c0 = tx*4;
    float acc[4][4] = {};
    int n = g_cnt[c];
    const float* mu = g_means + (size_t)pc*FF;
    for (int m = 0; m < n; m++){
        int t = g_members[c*TT + m];
        __syncthreads();
        if (tid < 64)       af[tid]    = sf[((size_t)p*TT+t)*FF + tf*64 + tid]      - mu[tf*64 + tid];
        else if (tid < 128) ag[tid-64] = sf[((size_t)p*TT+t)*FF + tg*64 + (tid-64)] - mu[tg*64 + (tid-64)];
        __syncthreads();
        float a[4], b[4];
        #pragma unroll
        for (int i = 0; i < 4; i++) a[i] = af[r0+i];
        #pragma unroll
        for (int j = 0; j < 4; j++) b[j] = ag[c0+j];
        #pragma unroll
        for (int i = 0; i < 4; i++)
            #pragma unroll
            for (int j = 0; j < 4; j++) acc[i][j] += a[i]*b[j];
    }
    float ss = g_sclS[c], st = g_sclT[c];
    float* dst = g_M + (size_t)pc*FF*FF;
    const float* tk = g_task + (size_t)p*FF*FF;
    #pragma unroll
    for (int i = 0; i < 4; i++)
        #pragma unroll
        for (int j = 0; j < 4; j++){
            int fr = tf*64 + r0 + i, gc = tg*64 + c0 + j;
            float v = ss*acc[i][j] + st*tk[(size_t)fr*FF + gc] + ((fr == gc) ? 1.0f : 0.0f);
            dst[(size_t)fr*FF + gc] = v;
        }
}

// ------------------------- zero W -------------------------
__global__ void zeroW_k(){
    size_t n4 = (size_t)NM*FF*FF/4;
    float4 z = {0,0,0,0};
    float4* w = (float4*)g_W;
    for (size_t i = (size_t)blockIdx.x*blockDim.x + threadIdx.x; i < n4;
         i += (size_t)gridDim.x*blockDim.x)
        w[i] = z;
}

// ------------------------- 64x64 shared-tile helpers (pitch 65) -------------------------
#define PT 65
__device__ __forceinline__ void ldt(float* dst, const float* g, int tid){
    #pragma unroll 4
    for (int e = tid; e < 4096; e += 256){
        int r = e >> 6, c = e & 63;
        dst[r*PT + c] = g[(size_t)r*FF + c];
    }
}
// acc[i][.] += A[r0+i][k] * B[c0+j][k]   (NT)
__device__ __forceinline__ void g64_nt(const float* A, const float* B,
                                       unsigned long long acc[4][2], int r0, int c0){
    #pragma unroll 4
    for (int k = 0; k < 64; k++){
        unsigned long long b01 = pk2(B[(c0+0)*PT+k], B[(c0+1)*PT+k]);
        unsigned long long b23 = pk2(B[(c0+2)*PT+k], B[(c0+3)*PT+k]);
        #pragma unroll
        for (int i = 0; i < 4; i++){
            float a = A[(r0+i)*PT+k];
            unsigned long long aa = pk2(a, a);
            fma2(acc[i][0], aa, b01);
            fma2(acc[i][1], aa, b23);
        }
    }
}
// acc[i][.] += A[r0+i][k] * B[k][c0+j]   (NN)
__device__ __forceinline__ void g64_nn(const float* A, const float* B,
                                       unsigned long long acc[4][2], int r0, int c0){
    #pragma unroll 4
    for (int k = 0; k < 64; k++){
        unsigned long long b01 = pk2(B[k*PT+c0+0], B[k*PT+c0+1]);
        unsigned long long b23 = pk2(B[k*PT+c0+2], B[k*PT+c0+3]);
        #pragma unroll
        for (int i = 0; i < 4; i++){
            float a = A[(r0+i)*PT+k];
            unsigned long long aa = pk2(a, a);
            fma2(acc[i][0], aa, b01);
            fma2(acc[i][1], aa, b23);
        }
    }
}

// ------------------------- blocked Cholesky + W = L^{-1} (one CTA per matrix) -------------
__global__ void __launch_bounds__(256) cholinv_k(){
    extern __shared__ float sm[];
    float* sA = sm;               // 64*65
    float* sB = sm + 64*PT;       // 64*65
    float* sC = sm + 2*64*PT;     // 64*65
    int mat = blockIdx.x;
    float* M = g_M + (size_t)mat*FF*FF;
    float* W = g_W + (size_t)mat*FF*FF;
    int tid = threadIdx.x, tx = tid & 15, ty = tid >> 4;
    int r0 = ty*4, c0 = tx*4;

    // ============ Phase A: blocked Cholesky (right-looking) ============
    for (int j = 0; j < 8; j++){
        ldt(sA, M + (size_t)(j*64)*FF + j*64, tid);
        __syncthreads();
        // unblocked Cholesky on sA (lower)
        for (int k = 0; k < 64; k++){
            if (tid == 0) sA[k*PT+k] = sqrtf(sA[k*PT+k]);
            __syncthreads();
            float dinv = 1.0f / sA[k*PT+k];
            for (int r = k+1+tid; r < 64; r += 256) sA[r*PT+k] *= dinv;
            __syncthreads();
            for (int e = tid; e < 4096; e += 256){
                int r = e >> 6, c = e & 63;
                if (r > k && c > k && c <= r) sA[r*PT+c] -= sA[r*PT+k]*sA[c*PT+k];
            }
            __syncthreads();
        }
        // triangular inverse of L_jj -> sB (upper zero)
        for (int e = tid; e < 4096; e += 256) sB[(e>>6)*PT + (e&63)] = 0.0f;
        __syncthreads();
        if (tid < 64){
            int c = tid;
            sB[c*PT+c] = 1.0f / sA[c*PT+c];
            for (int r = c+1; r < 64; r++){
                float s = 0.0f;
                for (int k2 = c; k2 < r; k2++) s += sA[r*PT+k2] * sB[k2*PT+c];
                sB[r*PT+c] = -s / sA[r*PT+r];
            }
        }
        __syncthreads();
        // store Linv_jj into W diagonal block
        for (int e = tid; e < 4096; e += 256){
            int r = e >> 6, c = e & 63;
            W[(size_t)(j*64 + r)*FF + j*64 + c] = sB[r*PT+c];
        }
        // panel: L_ij = A_ij * Linv_jj^T
        for (int i = j+1; i < 8; i++){
            __syncthreads();
            ldt(sC, M + (size_t)(i*64)*FF + j*64, tid);
            __syncthreads();
            unsigned long long acc[4][2] = {};
            g64_nt(sC, sB, acc, r0, c0);
            __syncthreads();
            #pragma unroll
            for (int ii = 0; ii < 4; ii++){
                float v0,v1,v2,v3;
                up2(acc[ii][0], v0, v1);
                up2(acc[ii][1], v2, v3);
                float4 v = {v0,v1,v2,v3};
                *(float4*)&M[(size_t)(i*64 + r0 + ii)*FF + j*64 + c0] = v;
            }
        }
        // trailing update: A_ik -= L_ij * L_kj^T
        for (int i = j+1; i < 8; i++)
            for (int kk = j+1; kk <= i; kk++){
                __syncthreads();
                ldt(sA, M + (size_t)(i*64)*FF + j*64, tid);   // L_ij
                ldt(sB, M + (size_t)(kk*64)*FF + j*64, tid);  // L_kj
                __syncthreads();
                unsigned long long acc[4][2] = {};
                g64_nt(sA, sB, acc, r0, c0);
                #pragma unroll
                for (int ii = 0; ii < 4; ii++){
                    float v0,v1,v2,v3;
                    up2(acc[ii][0], v0, v1);
                    up2(acc[ii][1], v2, v3);
                    float4* dst = (float4*)&M[(size_t)(i*64 + r0 + ii)*FF + kk*64 + c0];
                    float4 v = *dst;
                    v.x -= v0; v.y -= v1; v.z -= v2; v.w -= v3;
                    *dst = v;
                }
            }
        __syncthreads();
    }

    // ============ Phase B: W_ij = -Linv_ii * (sum_{k=j..i-1} L_ik W_kj) ============
    for (int j = 0; j < 8; j++)
        for (int i = j+1; i < 8; i++){
            unsigned long long acc[4][2] = {};
            for (int k = j; k < i; k++){
                __syncthreads();
                ldt(sA, M + (size_t)(i*64)*FF + k*64, tid);   // L_ik
                ldt(sB, W + (size_t)(k*64)*FF + j*64, tid);   // W_kj
                __syncthreads();
                g64_nn(sA, sB, acc, r0, c0);
            }
            __syncthreads();
            // S -> sC
            #pragma unroll
            for (int ii = 0; ii < 4; ii++){
                float v0,v1,v2,v3;
                up2(acc[ii][0], v0, v1);
                up2(acc[ii][1], v2, v3);
                sC[(r0+ii)*PT + c0 + 0] = v0;
                sC[(r0+ii)*PT + c0 + 1] = v1;
                sC[(r0+ii)*PT + c0 + 2] = v2;
                sC[(r0+ii)*PT + c0 + 3] = v3;
            }
            ldt(sA, W + (size_t)(i*64)*FF + i*64, tid);       // Linv_ii
            __syncthreads();
            unsigned long long acc2[4][2] = {};
            g64_nn(sA, sC, acc2, r0, c0);
            #pragma unroll
            for (int ii = 0; ii < 4; ii++){
                float v0,v1,v2,v3;
                up2(acc2[ii][0], v0, v1);
                up2(acc2[ii][1], v2, v3);
                float4 v = {-v0,-v1,-v2,-v3};
                *(float4*)&W[(size_t)(i*64 + r0 + ii)*FF + j*64 + c0] = v;
            }
            __syncthreads();
        }
}

// ------------------------- quad kernel: ||W (mu - x)||^2 -------------------------
// grid (8 qchunks, 160 pc), 256 threads. 128-row x 128-query tiles, 8x8 fragments.
#define WP 132
#define DP 130
__global__ void __launch_bounds__(256) quad_k(const float* __restrict__ qf){
    extern __shared__ float sm[];
    float* sW = sm;                     // [64][WP] transposed: sW[k][r]
    float* sD = sm + 64*WP;             // [64][DP]: sD[k][q]
    float* red = sm + 64*WP + 64*DP;    // [16][128]
    int pc = blockIdx.y;
    int p = pc / CC, c = pc % CC;
    int qbase = blockIdx.x * 128;
    int tid = threadIdx.x, tx = tid & 15, ty = tid >> 4;
    const float* Wg = g_W + (size_t)pc*FF*FF;
    const float* mu = g_means + (size_t)pc*FF;
    const float* xq = qf + ((size_t)p*QQ + qbase)*FF;
    unsigned long long qs[4] = {0,0,0,0};

    for (int rb = 0; rb < 4; rb++){
        unsigned long long acc[8][4];
        #pragma unroll
        for (int i = 0; i < 8; i++)
            #pragma unroll
            for (int j = 0; j < 4; j++) acc[i][j] = 0ULL;
        int nkt = 2*rb + 2;
        for (int kt = 0; kt < nkt; kt++){
            int k0 = kt*64;
            __syncthreads();
            #pragma unroll 4
            for (int idx = tid; idx < 128*64; idx += 256){
                int r = idx >> 6, k = idx & 63;
                sW[k*WP + r] = Wg[(size_t)(rb*128 + r)*FF + k0 + k];
            }
            #pragma unroll 4
            for (int idx = tid; idx < 128*64; idx += 256){
                int q = idx >> 6, k = idx & 63;
                sD[k*DP + q] = mu[k0+k] - xq[(size_t)q*FF + k0 + k];
            }
            __syncthreads();
            #pragma unroll 4
            for (int k = 0; k < 64; k++){
                float4 w0 = *(const float4*)&sW[k*WP + ty*8];
                float4 w1 = *(const float4*)&sW[k*WP + ty*8 + 4];
                unsigned long long d[4];
                #pragma unroll
                for (int j = 0; j < 4; j++)
                    d[j] = *(const unsigned long long*)&sD[k*DP + j*32 + tx*2];
                unsigned long long a;
                a = pk2(w0.x,w0.x);
                #pragma unroll
                for (int j=0;j<4;j++) fma2(acc[0][j], a, d[j]);
                a = pk2(w0.y,w0.y);
                #pragma unroll
                for (int j=0;j<4;j++) fma2(acc[1][j], a, d[j]);
                a = pk2(w0.z,w0.z);
                #pragma unroll
                for (int j=0;j<4;j++) fma2(acc[2][j], a, d[j]);
                a = pk2(w0.w,w0.w);
                #pragma unroll
                for (int j=0;j<4;j++) fma2(acc[3][j], a, d[j]);
                a = pk2(w1.x,w1.x);
                #pragma unroll
                for (int j=0;j<4;j++) fma2(acc[4][j], a, d[j]);
                a = pk2(w1.y,w1.y);
                #pragma unroll
                for (int j=0;j<4;j++) fma2(acc[5][j], a, d[j]);
                a = pk2(w1.z,w1.z);
                #pragma unroll
                for (int j=0;j<4;j++) fma2(acc[6][j], a, d[j]);
                a = pk2(w1.w,w1.w);
                #pragma unroll
                for (int j=0;j<4;j++) fma2(acc[7][j], a, d[j]);
            }
        }
        #pragma unroll
        for (int i = 0; i < 8; i++)
            #pragma unroll
            for (int j = 0; j < 4; j++) fma2(qs[j], acc[i][j], acc[i][j]);
    }

    // reduce qs across ty (16 partials per query)
    __syncthreads();
    #pragma unroll
    for (int j = 0; j < 4; j++){
        float lo, hi;
        up2(qs[j], lo, hi);
        red[ty*128 + j*32 + tx*2]     = lo;
        red[ty*128 + j*32 + tx*2 + 1] = hi;
    }
    __syncthreads();
    for (int s = 8; s; s >>= 1){
        if (ty < s){
            #pragma unroll
            for (int j = 0; j < 4; j++){
                int q = j*32 + tx*2;
                red[ty*128+q]   += red[(ty+s)*128+q];
                red[ty*128+q+1] += red[(ty+s)*128+q+1];
            }
        }
        __syncthreads();
    }
    if (tid < 128)
        g_quad[((size_t)p*QQ + qbase + tid)*CC + c] = red[tid];
}

// ------------------------- final logits + means copy -------------------------
__global__ void logits_k(float* out){
    int q = blockIdx.x;
    int c = threadIdx.x;
    if (c < CC){
        float s = 0.0f;
        #pragma unroll
        for (int p = 0; p < PP; p++) s += g_quad[((size_t)p*QQ + q)*CC + c];
        out[q*CC + c] = -s * (1.0f/PP);
    }
}
__global__ void copymeans_k(float* out){
    for (int i = blockIdx.x*blockDim.x + threadIdx.x; i < NM*FF; i += gridDim.x*blockDim.x)
        out[QQ*CC + i] = g_means[i];
}

// ------------------------- launch -------------------------
extern "C" void kernel_launch(void* const* d_in, const int* in_sizes, int n_in,
                              void* d_out, int out_size) {
    const float* sf  = (const float*)d_in[0];
    const int*   lab = (const int*)d_in[1];
    const float* qf  = (const float*)d_in[2];
    float* out = (float*)d_out;

    const int CHOL_SMEM = 3*64*PT*(int)sizeof(float);                   // 49920
    const int QUAD_SMEM = (64*WP + 64*DP + 16*128)*(int)sizeof(float);  // 75264
    cudaFuncSetAttribute(cholinv_k, cudaFuncAttributeMaxDynamicSharedMemorySize, CHOL_SMEM);
    cudaFuncSetAttribute(quad_k,    cudaFuncAttributeMaxDynamicSharedMemorySize, QUAD_SMEM);

    setup_k<<<1, 32>>>(lab);
    means_k<<<NM, 256>>>(sf);
    tm_k<<<PP, 256>>>(sf);
    taskcov_k<<<dim3(64, PP), 256>>>(sf);
    buildM_k<<<dim3(64, NM), 256>>>(sf);
    zeroW_k<<<2048, 256>>>();
    cholinv_k<<<NM, 256, CHOL_SMEM>>>();
    quad_k<<<dim3(8, NM), 256, QUAD_SMEM>>>(qf);
    logits_k<<<QQ, 32>>>(out);
    if (out_size >= QQ*CC + NM*FF)
        copymeans_k<<<160, 512>>>(out);
}

// round 3
// speedup vs baseline: 1.0034x; 1.0034x over previous
#include <cuda_runtime.h>
#include <math.h>

#define PP 8
#define TT 200
#define FF 512
#define CC 20
#define QQ 1024
#define NM (PP*CC)   // 160 matrices
typedef unsigned long long ULL;

// ------------------------- device scratch -------------------------
__device__ float g_means[NM*FF];
__device__ float g_tm[PP*FF];
__device__ float g_task[(size_t)PP*FF*FF];
__device__ float g_M[(size_t)NM*FF*FF];            // cov_reg -> L (in place)
__device__ float g_W[(size_t)NM*FF*FF];            // W = L^{-1}
__device__ float g_quad[(size_t)PP*QQ*CC];
__device__ int   g_members[CC*TT];
__device__ int   g_cnt[CC];
__device__ float g_icnts[CC], g_sclS[CC], g_sclT[CC];

// ------------------------- f32x2 helpers -------------------------
__device__ __forceinline__ ULL pk2(float lo, float hi){
    ULL r; asm("mov.b64 %0, {%1,%2};" : "=l"(r) : "f"(lo), "f"(hi)); return r;
}
__device__ __forceinline__ void up2(ULL v, float &a, float &b){
    asm("mov.b64 {%0,%1}, %2;" : "=f"(a), "=f"(b) : "l"(v));
}
__device__ __forceinline__ void fma2(ULL &d, ULL a, ULL b){
    asm("fma.rn.f32x2 %0, %1, %2, %0;" : "+l"(d) : "l"(a), "l"(b));
}

// ------------------------- setup -------------------------
__global__ void setup_k(const int* __restrict__ lab_raw){
    if (threadIdx.x == 0 && blockIdx.x == 0){
        bool odd_all_zero = true;
        for (int t = 1; t < 200; t += 2) if (lab_raw[t] != 0) odd_all_zero = false;
        bool even_has_big = false;
        for (int t = 0; t < 200; t += 2) if (lab_raw[t] > 0) even_has_big = true;
        bool is64 = odd_all_zero && even_has_big;

        int cnt[CC];
        #pragma unroll
        for (int c = 0; c < CC; c++) cnt[c] = 0;
        for (int t = 0; t < TT; t++){
            int cc = is64 ? lab_raw[2*t] : lab_raw[t];
            if (cc < 0) cc = 0; if (cc >= CC) cc = CC-1;
            g_members[cc*TT + cnt[cc]] = t;
            cnt[cc]++;
        }
        for (int c = 0; c < CC; c++){
            g_cnt[c] = cnt[c];
            float cs  = fmaxf((float)cnt[c], 1.0f);
            g_icnts[c] = 1.0f / cs;
            float lam = cs / (cs + 1.0f);
            g_sclS[c] = lam / fmaxf((float)cnt[c] - 1.0f, 1.0f);
            g_sclT[c] = 1.0f - lam;
        }
    }
}

// ------------------------- class means -------------------------
__global__ void means_k(const float* __restrict__ sf){
    int pc = blockIdx.x;
    int p = pc / CC, c = pc % CC;
    int n = g_cnt[c];
    float ic = g_icnts[c];
    for (int f = threadIdx.x; f < FF; f += blockDim.x){
        float s = 0.0f;
        for (int m = 0; m < n; m++){
            int t = g_members[c*TT + m];
            s += sf[((size_t)p*TT + t)*FF + f];
        }
        g_means[(size_t)pc*FF + f] = s * ic;
    }
}

// ------------------------- task mean -------------------------
__global__ void tm_k(const float* __restrict__ sf){
    int p = blockIdx.x;
    for (int f = threadIdx.x; f < FF; f += blockDim.x){
        float s = 0.0f;
        for (int t = 0; t < TT; t++) s += sf[((size_t)p*TT + t)*FF + f];
        g_tm[p*FF + f] = s * (1.0f/TT);
    }
}

// ------------------------- task covariance (symmetric, batched staging) -----------------
__global__ void taskcov_k(const float* __restrict__ sf){
    int tile = blockIdx.x;          // 0..35 (tg<=tf)
    int p    = blockIdx.y;
    int tf = 0, rem = tile;
    while (rem >= tf+1){ rem -= tf+1; tf++; }
    int tg = rem;
    __shared__ float af[8][68], ag[8][68];
    int tid = threadIdx.x, tx = tid & 15, ty = tid >> 4;
    int r0 = ty*4, c0 = tx*4;
    float acc[4][4] = {};
    const float* tmv = g_tm + p*FF;
    for (int t0 = 0; t0 < TT; t0 += 8){
        __syncthreads();
        #pragma unroll
        for (int ii = 0; ii < 2; ii++){
            int idx = ii*256 + tid;
            int s = idx >> 6, f = idx & 63;
            const float* row = sf + ((size_t)p*TT + t0 + s)*FF;
            af[s][f] = row[tf*64 + f] - tmv[tf*64 + f];
            ag[s][f] = row[tg*64 + f] - tmv[tg*64 + f];
        }
        __syncthreads();
        #pragma unroll
        for (int s = 0; s < 8; s++){
            float a[4], b[4];
            #pragma unroll
            for (int i = 0; i < 4; i++) a[i] = af[s][r0+i];
            #pragma unroll
            for (int j = 0; j < 4; j++) b[j] = ag[s][c0+j];
            #pragma unroll
            for (int i = 0; i < 4; i++)
                #pragma unroll
                for (int j = 0; j < 4; j++) acc[i][j] += a[i]*b[j];
        }
    }
    const float inv = 1.0f/(TT-1);
    float* dst = g_task + (size_t)p*FF*FF;
    #pragma unroll
    for (int i = 0; i < 4; i++)
        #pragma unroll
        for (int j = 0; j < 4; j++){
            int fr = tf*64 + r0 + i, gc = tg*64 + c0 + j;
            float v = acc[i][j]*inv;
            dst[(size_t)fr*FF + gc] = v;
            dst[(size_t)gc*FF + fr] = v;
        }
}

// ------------------------- cov_reg (symmetric, batched staging) -------------------------
__global__ void buildM_k(const float* __restrict__ sf){
    int tile = blockIdx.x;          // 0..35
    int pc   = blockIdx.y;          // 0..159
    int p = pc / CC, c = pc % CC;
    int tf = 0, rem = tile;
    while (rem >= tf+1){ rem -= tf+1; tf++; }
    int tg = rem;
    __shared__ float af[4][68], ag[4][68];
    int tid = threadIdx.x, tx = tid & 15, ty = tid >> 4;
    int r0 = ty*4, c0 = tx*4;
    float acc[4][4] = {};
    int n = g_cnt[c];
    const float* mu = g_means + (size_t)pc*FF;
    for (int m0 = 0; m0 < n; m0 += 4){
        __syncthreads();
        {
            int s = tid >> 6, f = tid & 63;
            int m = m0 + s;
            float va = 0.0f, vg = 0.0f;
            if (m < n){
                int t = g_members[c*TT + m];
                const float* row = sf + ((size_t)p*TT + t)*FF;
                va = row[tf*64 + f] - mu[tf*64 + f];
                vg = row[tg*64 + f] - mu[tg*64 + f];
            }
            af[s][f] = va; ag[s][f] = vg;
        }
        __syncthreads();
        #pragma unroll
        for (int s = 0; s < 4; s++){
            float a[4], b[4];
            #pragma unroll
            for (int i = 0; i < 4; i++) a[i] = af[s][r0+i];
            #pragma unroll
            for (int j = 0; j < 4; j++) b[j] = ag[s][c0+j];
            #pragma unroll
            for (int i = 0; i < 4; i++)
                #pragma unroll
                for (int j = 0; j < 4; j++) acc[i][j] += a[i]*b[j];
        }
    }
    float ss = g_sclS[c], st = g_sclT[c];
    float* dst = g_M + (size_t)pc*FF*FF;
    const float* tk = g_task + (size_t)p*FF*FF;
    #pragma unroll
    for (int i = 0; i < 4; i++)
        #pragma unroll
        for (int j = 0; j < 4; j++){
            int fr = tf*64 + r0 + i, gc = tg*64 + c0 + j;
            float v = ss*acc[i][j] + st*tk[(size_t)fr*FF + gc] + ((fr == gc) ? 1.0f : 0.0f);
            dst[(size_t)fr*FF + gc] = v;
            dst[(size_t)gc*FF + fr] = v;
        }
}

// -------- zero only the 4 above-diagonal 64-blocks per matrix that quad_k reads --------
__global__ void zeroWu_k(){
    int rb  = blockIdx.x;           // 0..3
    int mat = blockIdx.y;
    float4 z = {0,0,0,0};
    for (int e = threadIdx.x; e < 64*16; e += 256){
        int r = e >> 4, c4 = e & 15;
        int row = rb*128 + r, col = rb*128 + 64 + c4*4;
        *(float4*)&g_W[(size_t)mat*FF*FF + (size_t)row*FF + col] = z;
    }
}

// ------------------------- 64x64 helpers (pitch 65) -------------------------
#define PT 65
__device__ __forceinline__ void ldt(float* dst, const float* g, int tid){
    #pragma unroll 4
    for (int e = tid; e < 4096; e += 256){
        int r = e >> 6, c = e & 63;
        dst[r*PT + c] = g[(size_t)r*FF + c];
    }
}
__device__ __forceinline__ void g64_nt(const float* A, const float* B,
                                       ULL acc[4][2], int r0, int c0){
    #pragma unroll 4
    for (int k = 0; k < 64; k++){
        ULL b01 = pk2(B[(c0+0)*PT+k], B[(c0+1)*PT+k]);
        ULL b23 = pk2(B[(c0+2)*PT+k], B[(c0+3)*PT+k]);
        #pragma unroll
        for (int i = 0; i < 4; i++){
            float a = A[(r0+i)*PT+k];
            ULL aa = pk2(a, a);
            fma2(acc[i][0], aa, b01);
            fma2(acc[i][1], aa, b23);
        }
    }
}
__device__ __forceinline__ void g64_nn(const float* A, const float* B,
                                       ULL acc[4][2], int r0, int c0){
    #pragma unroll 4
    for (int k = 0; k < 64; k++){
        ULL b01 = pk2(B[k*PT+c0+0], B[k*PT+c0+1]);
        ULL b23 = pk2(B[k*PT+c0+2], B[k*PT+c0+3]);
        #pragma unroll
        for (int i = 0; i < 4; i++){
            float a = A[(r0+i)*PT+k];
            ULL aa = pk2(a, a);
            fma2(acc[i][0], aa, b01);
            fma2(acc[i][1], aa, b23);
        }
    }
}

// ------------------------- blocked LDL^T Cholesky + W = L^{-1} -------------------------
__global__ void __launch_bounds__(256) cholinv_k(){
    extern __shared__ float sm[];
    float* sA = sm;
    float* sB = sm + 64*PT;
    float* sC = sm + 2*64*PT;
    int mat = blockIdx.x;
    float* M = g_M + (size_t)mat*FF*FF;
    float* W = g_W + (size_t)mat*FF*FF;
    int tid = threadIdx.x, tx = tid & 15, ty = tid >> 4;
    int r0 = ty*4, c0 = tx*4;

    // ============ Phase A ============
    for (int j = 0; j < 8; j++){
        ldt(sA, M + (size_t)(j*64)*FF + j*64, tid);
        __syncthreads();
        // LDL^T elimination: 1 barrier per column
        for (int k = 0; k < 64; k++){
            float pinv = 1.0f / sA[k*PT+k];
            #pragma unroll 4
            for (int e = tid; e < 4096; e += 256){
                int r = e >> 6, cc = e & 63;
                if (r > k && cc > k && cc <= r)
                    sA[r*PT+cc] -= sA[r*PT+k]*sA[cc*PT+k]*pinv;
            }
            __syncthreads();
        }
        // rescale to Cholesky L: L[r][c] = A[r][c]*rsqrt(D[c]); diag -> sqrt(D)
        if (tid < 64) sC[tid] = rsqrtf(sA[tid*PT+tid]);
        __syncthreads();
        #pragma unroll 4
        for (int e = tid; e < 4096; e += 256){
            int r = e >> 6, cc = e & 63;
            if (cc <= r) sA[r*PT+cc] *= sC[cc];
        }
        __syncthreads();

        // triangular inverse of L_jj -> sB, 4 lanes per column
        #pragma unroll 4
        for (int e = tid; e < 4096; e += 256) sB[(e>>6)*PT + (e&63)] = 0.0f;
        __syncthreads();
        {
            int c = tid >> 2, s = tid & 3;
            unsigned gmask = 0xFu << ((tid & 31) & ~3);
            float dv = 1.0f / sA[c*PT+c];
            if (s == 0) sB[c*PT+c] = dv;
            __syncwarp(gmask);
            for (int r = c+1; r < 64; r++){
                float part = 0.0f;
                for (int k2 = c + s; k2 < r; k2 += 4)
                    part += sA[r*PT+k2] * sB[k2*PT+c];
                part += __shfl_xor_sync(gmask, part, 1);
                part += __shfl_xor_sync(gmask, part, 2);
                if (s == 0) sB[r*PT+c] = -part / sA[r*PT+r];
                __syncwarp(gmask);
            }
        }
        __syncthreads();
        // store diag inverse
        #pragma unroll 4
        for (int e = tid; e < 4096; e += 256){
            int r = e >> 6, cc = e & 63;
            W[(size_t)(j*64 + r)*FF + j*64 + cc] = sB[r*PT+cc];
        }
        // panel: L_ij = A_ij * Linv_jj^T
        for (int i = j+1; i < 8; i++){
            __syncthreads();
            ldt(sC, M + (size_t)(i*64)*FF + j*64, tid);
            __syncthreads();
            ULL acc[4][2] = {};
            g64_nt(sC, sB, acc, r0, c0);
            #pragma unroll
            for (int ii = 0; ii < 4; ii++){
                float v0,v1,v2,v3;
                up2(acc[ii][0], v0, v1);
                up2(acc[ii][1], v2, v3);
                float4 v = {v0,v1,v2,v3};
                *(float4*)&M[(size_t)(i*64 + r0 + ii)*FF + j*64 + c0] = v;
            }
        }
        // trailing: A_ik -= L_ij L_kj^T  (L_ij cached in sA across kk)
        for (int i = j+1; i < 8; i++){
            __syncthreads();
            ldt(sA, M + (size_t)(i*64)*FF + j*64, tid);
            __syncthreads();
            for (int kk = j+1; kk <= i; kk++){
                ULL acc[4][2] = {};
                if (kk < i){
                    ldt(sC, M + (size_t)(kk*64)*FF + j*64, tid);
                    __syncthreads();
                    g64_nt(sA, sC, acc, r0, c0);
                } else {
                    g64_nt(sA, sA, acc, r0, c0);
                }
                #pragma unroll
                for (int ii = 0; ii < 4; ii++){
                    float v0,v1,v2,v3;
                    up2(acc[ii][0], v0, v1);
                    up2(acc[ii][1], v2, v3);
                    float4* dst = (float4*)&M[(size_t)(i*64 + r0 + ii)*FF + kk*64 + c0];
                    float4 v = *dst;
                    v.x -= v0; v.y -= v1; v.z -= v2; v.w -= v3;
                    *dst = v;
                }
                __syncthreads();
            }
        }
        __syncthreads();
    }

    // ============ Phase B: W_ij = -Linv_ii * (sum_{k=j..i-1} L_ik W_kj) ============
    for (int j = 0; j < 8; j++)
        for (int i = j+1; i < 8; i++){
            ULL acc[4][2] = {};
            for (int k = j; k < i; k++){
                __syncthreads();
                ldt(sA, M + (size_t)(i*64)*FF + k*64, tid);
                ldt(sB, W + (size_t)(k*64)*FF + j*64, tid);
                __syncthreads();
                g64_nn(sA, sB, acc, r0, c0);
            }
            __syncthreads();
            #pragma unroll
            for (int ii = 0; ii < 4; ii++){
                float v0,v1,v2,v3;
                up2(acc[ii][0], v0, v1);
                up2(acc[ii][1], v2, v3);
                sC[(r0+ii)*PT + c0 + 0] = v0;
                sC[(r0+ii)*PT + c0 + 1] = v1;
                sC[(r0+ii)*PT + c0 + 2] = v2;
                sC[(r0+ii)*PT + c0 + 3] = v3;
            }
            ldt(sA, W + (size_t)(i*64)*FF + i*64, tid);
            __syncthreads();
            ULL acc2[4][2] = {};
            g64_nn(sA, sC, acc2, r0, c0);
            #pragma unroll
            for (int ii = 0; ii < 4; ii++){
                float v0,v1,v2,v3;
                up2(acc2[ii][0], v0, v1);
                up2(acc2[ii][1], v2, v3);
                float4 v = {-v0,-v1,-v2,-v3};
                *(float4*)&W[(size_t)(i*64 + r0 + ii)*FF + j*64 + c0] = v;
            }
            __syncthreads();
        }
}

// ------------------------- quad: ||W (mu - x)||^2 -------------------------
// sW stored as pre-duplicated f32x2 pairs [r][k] (pitch 65 in ULL units).
#define DP 130
__global__ void __launch_bounds__(256) quad_k(const float* __restrict__ qf){
    extern __shared__ char smq[];
    ULL*   sW2 = (ULL*)smq;                          // 128*65 ULL = 66560 B
    float* sD  = (float*)(smq + 128*65*8);           // 64*130  f  = 33280 B
    float* red = sD + 64*DP;                         // 16*128  f  =  8192 B
    int pc = blockIdx.y;
    int p = pc / CC, c = pc % CC;
    int qbase = blockIdx.x * 128;
    int tid = threadIdx.x, tx = tid & 15, ty = tid >> 4;
    const float* Wg = g_W + (size_t)pc*FF*FF;
    const float* mu = g_means + (size_t)pc*FF;
    const float* xq = qf + ((size_t)p*QQ + qbase)*FF;
    ULL qs[4] = {0,0,0,0};

    for (int rb = 0; rb < 4; rb++){
        ULL acc[8][4];
        #pragma unroll
        for (int i = 0; i < 8; i++)
            #pragma unroll
            for (int j = 0; j < 4; j++) acc[i][j] = 0ULL;
        int nkt = 2*rb + 2;
        for (int kt = 0; kt < nkt; kt++){
            int k0 = kt*64;
            __syncthreads();
            #pragma unroll 4
            for (int idx = tid; idx < 128*64; idx += 256){
                int r = idx >> 6, k = idx & 63;
                float v = Wg[(size_t)(rb*128 + r)*FF + k0 + k];
                sW2[r*65 + k] = pk2(v, v);
            }
            #pragma unroll 4
            for (int idx = tid; idx < 128*64; idx += 256){
                int q = idx >> 6, k = idx & 63;
                sD[k*DP + q] = mu[k0+k] - xq[(size_t)q*FF + k0 + k];
            }
            __syncthreads();
            #pragma unroll 4
            for (int k = 0; k < 64; k++){
                ULL d[4];
                #pragma unroll
                for (int j = 0; j < 4; j++)
                    d[j] = *(const ULL*)&sD[k*DP + j*32 + tx*2];
                #pragma unroll
                for (int i = 0; i < 8; i++){
                    ULL w2 = sW2[(ty*8 + i)*65 + k];
                    #pragma unroll
                    for (int j = 0; j < 4; j++) fma2(acc[i][j], w2, d[j]);
                }
            }
        }
        #pragma unroll
        for (int i = 0; i < 8; i++)
            #pragma unroll
            for (int j = 0; j < 4; j++) fma2(qs[j], acc[i][j], acc[i][j]);
    }

    __syncthreads();
    #pragma unroll
    for (int j = 0; j < 4; j++){
        float lo, hi;
        up2(qs[j], lo, hi);
        red[ty*128 + j*32 + tx*2]     = lo;
        red[ty*128 + j*32 + tx*2 + 1] = hi;
    }
    __syncthreads();
    for (int s = 8; s; s >>= 1){
        if (ty < s){
            #pragma unroll
            for (int j = 0; j < 4; j++){
                int q = j*32 + tx*2;
                red[ty*128+q]   += red[(ty+s)*128+q];
                red[ty*128+q+1] += red[(ty+s)*128+q+1];
            }
        }
        __syncthreads();
    }
    if (tid < 128)
        g_quad[((size_t)p*QQ + qbase + tid)*CC + c] = red[tid];
}

// ------------------------- final outputs -------------------------
__global__ void logits_k(float* out){
    int q = blockIdx.x;
    int c = threadIdx.x;
    if (c < CC){
        float s = 0.0f;
        #pragma unroll
        for (int p = 0; p < PP; p++) s += g_quad[((size_t)p*QQ + q)*CC + c];
        out[q*CC + c] = -s * (1.0f/PP);
    }
}
__global__ void copymeans_k(float* out){
    for (int i = blockIdx.x*blockDim.x + threadIdx.x; i < NM*FF; i += gridDim.x*blockDim.x)
        out[QQ*CC + i] = g_means[i];
}

// ------------------------- launch -------------------------
extern "C" void kernel_launch(void* const* d_in, const int* in_sizes, int n_in,
                              void* d_out, int out_size) {
    const float* sf  = (const float*)d_in[0];
    const int*   lab = (const int*)d_in[1];
    const float* qf  = (const float*)d_in[2];
    float* out = (float*)d_out;

    const int CHOL_SMEM = 3*64*PT*(int)sizeof(float);               // 49920
    const int QUAD_SMEM = 128*65*8 + 64*DP*4 + 16*128*4;            // 108032
    cudaFuncSetAttribute(cholinv_k, cudaFuncAttributeMaxDynamicSharedMemorySize, CHOL_SMEM);
    cudaFuncSetAttribute(quad_k,    cudaFuncAttributeMaxDynamicSharedMemorySize, QUAD_SMEM);

    setup_k<<<1, 32>>>(lab);
    means_k<<<NM, 256>>>(sf);
    tm_k<<<PP, 256>>>(sf);
    taskcov_k<<<dim3(36, PP), 256>>>(sf);
    buildM_k<<<dim3(36, NM), 256>>>(sf);
    zeroWu_k<<<dim3(4, NM), 256>>>();
    cholinv_k<<<NM, 256, CHOL_SMEM>>>();
    quad_k<<<dim3(8, NM), 256, QUAD_SMEM>>>(qf);
    logits_k<<<QQ, 32>>>(out);
    if (out_size >= QQ*CC + NM*FF)
        copymeans_k<<<160, 512>>>(out);
}

// round 4
// speedup vs baseline: 1.0875x; 1.0838x over previous
#include <cuda_runtime.h>
#include <math.h>

#define PP 8
#define TT 200
#define FF 512
#define CC 20
#define QQ 1024
#define NM (PP*CC)
typedef unsigned long long ULL;

// ------------------------- device scratch -------------------------
__device__ float g_means[NM*FF];
__device__ float g_tm[PP*FF];
__device__ float g_task[(size_t)PP*FF*FF];
__device__ float g_M[(size_t)NM*FF*FF];            // cov_reg -> L (in place)
__device__ float g_W[(size_t)NM*FF*FF];            // W = L^{-1}
__device__ float g_quad[(size_t)PP*QQ*CC];
__device__ int   g_members[CC*TT];
__device__ int   g_cnt[CC];
__device__ float g_icnts[CC], g_sclS[CC], g_sclT[CC];

// ------------------------- f32x2 helpers -------------------------
__device__ __forceinline__ ULL pk2(float lo, float hi){
    ULL r; asm("mov.b64 %0, {%1,%2};" : "=l"(r) : "f"(lo), "f"(hi)); return r;
}
__device__ __forceinline__ void up2(ULL v, float &a, float &b){
    asm("mov.b64 {%0,%1}, %2;" : "=f"(a), "=f"(b) : "l"(v));
}
__device__ __forceinline__ void fma2(ULL &d, ULL a, ULL b){
    asm("fma.rn.f32x2 %0, %1, %2, %0;" : "+l"(d) : "l"(a), "l"(b));
}

// ------------------------- setup -------------------------
__global__ void setup_k(const int* __restrict__ lab_raw){
    if (threadIdx.x == 0 && blockIdx.x == 0){
        bool odd_all_zero = true;
        for (int t = 1; t < 200; t += 2) if (lab_raw[t] != 0) odd_all_zero = false;
        bool even_has_big = false;
        for (int t = 0; t < 200; t += 2) if (lab_raw[t] > 0) even_has_big = true;
        bool is64 = odd_all_zero && even_has_big;

        int cnt[CC];
        #pragma unroll
        for (int c = 0; c < CC; c++) cnt[c] = 0;
        for (int t = 0; t < TT; t++){
            int cc = is64 ? lab_raw[2*t] : lab_raw[t];
            if (cc < 0) cc = 0; if (cc >= CC) cc = CC-1;
            g_members[cc*TT + cnt[cc]] = t;
            cnt[cc]++;
        }
        for (int c = 0; c < CC; c++){
            g_cnt[c] = cnt[c];
            float cs  = fmaxf((float)cnt[c], 1.0f);
            g_icnts[c] = 1.0f / cs;
            float lam = cs / (cs + 1.0f);
            g_sclS[c] = lam / fmaxf((float)cnt[c] - 1.0f, 1.0f);
            g_sclT[c] = 1.0f - lam;
        }
    }
}

// ------------------------- class means -------------------------
__global__ void means_k(const float* __restrict__ sf){
    int pc = blockIdx.x;
    int p = pc / CC, c = pc % CC;
    int n = g_cnt[c];
    float ic = g_icnts[c];
    for (int f = threadIdx.x; f < FF; f += blockDim.x){
        float s = 0.0f;
        for (int m = 0; m < n; m++){
            int t = g_members[c*TT + m];
            s += sf[((size_t)p*TT + t)*FF + f];
        }
        g_means[(size_t)pc*FF + f] = s * ic;
    }
}

// ------------------------- task mean -------------------------
__global__ void tm_k(const float* __restrict__ sf){
    int p = blockIdx.x;
    for (int f = threadIdx.x; f < FF; f += blockDim.x){
        float s = 0.0f;
        for (int t = 0; t < TT; t++) s += sf[((size_t)p*TT + t)*FF + f];
        g_tm[p*FF + f] = s * (1.0f/TT);
    }
}

// ------------------------- task covariance -------------------------
__global__ void taskcov_k(const float* __restrict__ sf){
    int tile = blockIdx.x;          // 0..35 (tg<=tf)
    int p    = blockIdx.y;
    int tf = 0, rem = tile;
    while (rem >= tf+1){ rem -= tf+1; tf++; }
    int tg = rem;
    __shared__ float af[8][68], ag[8][68];
    int tid = threadIdx.x, tx = tid & 15, ty = tid >> 4;
    int r0 = ty*4, c0 = tx*4;
    float acc[4][4] = {};
    const float* tmv = g_tm + p*FF;
    for (int t0 = 0; t0 < TT; t0 += 8){
        __syncthreads();
        #pragma unroll
        for (int ii = 0; ii < 2; ii++){
            int idx = ii*256 + tid;
            int s = idx >> 6, f = idx & 63;
            const float* row = sf + ((size_t)p*TT + t0 + s)*FF;
            af[s][f] = row[tf*64 + f] - tmv[tf*64 + f];
            ag[s][f] = row[tg*64 + f] - tmv[tg*64 + f];
        }
        __syncthreads();
        #pragma unroll
        for (int s = 0; s < 8; s++){
            float a[4], b[4];
            #pragma unroll
            for (int i = 0; i < 4; i++) a[i] = af[s][r0+i];
            #pragma unroll
            for (int j = 0; j < 4; j++) b[j] = ag[s][c0+j];
            #pragma unroll
            for (int i = 0; i < 4; i++)
                #pragma unroll
                for (int j = 0; j < 4; j++) acc[i][j] += a[i]*b[j];
        }
    }
    const float inv = 1.0f/(TT-1);
    float* dst = g_task + (size_t)p*FF*FF;
    #pragma unroll
    for (int i = 0; i < 4; i++)
        #pragma unroll
        for (int j = 0; j < 4; j++){
            int fr = tf*64 + r0 + i, gc = tg*64 + c0 + j;
            float v = acc[i][j]*inv;
            dst[(size_t)fr*FF + gc] = v;
            dst[(size_t)gc*FF + fr] = v;
        }
}

// ------------------------- cov_reg -------------------------
__global__ void buildM_k(const float* __restrict__ sf){
    int tile = blockIdx.x;          // 0..35
    int pc   = blockIdx.y;
    int p = pc / CC, c = pc % CC;
    int tf = 0, rem = tile;
    while (rem >= tf+1){ rem -= tf+1; tf++; }
    int tg = rem;
    __shared__ float af[4][68], ag[4][68];
    int tid = threadIdx.x, tx = tid & 15, ty = tid >> 4;
    int r0 = ty*4, c0 = tx*4;
    float acc[4][4] = {};
    int n = g_cnt[c];
    const float* mu = g_means + (size_t)pc*FF;
    for (int m0 = 0; m0 < n; m0 += 4){
        __syncthreads();
        {
            int s = tid >> 6, f = tid & 63;
            int m = m0 + s;
            float va = 0.0f, vg = 0.0f;
            if (m < n){
                int t = g_members[c*TT + m];
                const float* row = sf + ((size_t)p*TT + t)*FF;
                va = row[tf*64 + f] - mu[tf*64 + f];
                vg = row[tg*64 + f] - mu[tg*64 + f];
            }
            af[s][f] = va; ag[s][f] = vg;
        }
        __syncthreads();
        #pragma unroll
        for (int s = 0; s < 4; s++){
            float a[4], b[4];
            #pragma unroll
            for (int i = 0; i < 4; i++) a[i] = af[s][r0+i];
            #pragma unroll
            for (int j = 0; j < 4; j++) b[j] = ag[s][c0+j];
            #pragma unroll
            for (int i = 0; i < 4; i++)
                #pragma unroll
                for (int j = 0; j < 4; j++) acc[i][j] += a[i]*b[j];
        }
    }
    float ss = g_sclS[c], st = g_sclT[c];
    float* dst = g_M + (size_t)pc*FF*FF;
    const float* tk = g_task + (size_t)p*FF*FF;
    #pragma unroll
    for (int i = 0; i < 4; i++)
        #pragma unroll
        for (int j = 0; j < 4; j++){
            int fr = tf*64 + r0 + i, gc = tg*64 + c0 + j;
            float v = ss*acc[i][j] + st*tk[(size_t)fr*FF + gc] + ((fr == gc) ? 1.0f : 0.0f);
            dst[(size_t)fr*FF + gc] = v;
            dst[(size_t)gc*FF + fr] = v;
        }
}

// -------- zero the 4 above-diagonal 64-blocks per matrix that quad_k reads --------
__global__ void zeroWu_k(){
    int rb  = blockIdx.x;
    int mat = blockIdx.y;
    float4 z = {0,0,0,0};
    for (int e = threadIdx.x; e < 64*16; e += 256){
        int r = e >> 4, c4 = e & 15;
        int row = rb*128 + r, col = rb*128 + 64 + c4*4;
        *(float4*)&g_W[(size_t)mat*FF*FF + (size_t)row*FF + col] = z;
    }
}

// ------------------------- 64x64 helpers (pitch 65) -------------------------
#define PT 65
__device__ __forceinline__ void ldt(float* dst, const float* g, int tid){
    #pragma unroll 4
    for (int e = tid; e < 4096; e += 256){
        int r = e >> 6, c = e & 63;
        dst[r*PT + c] = g[(size_t)r*FF + c];
    }
}
__device__ __forceinline__ void g64_nt(const float* A, const float* B,
                                       ULL acc[4][2], int r0, int c0){
    #pragma unroll 4
    for (int k = 0; k < 64; k++){
        ULL b01 = pk2(B[(c0+0)*PT+k], B[(c0+1)*PT+k]);
        ULL b23 = pk2(B[(c0+2)*PT+k], B[(c0+3)*PT+k]);
        #pragma unroll
        for (int i = 0; i < 4; i++){
            float a = A[(r0+i)*PT+k];
            ULL aa = pk2(a, a);
            fma2(acc[i][0], aa, b01);
            fma2(acc[i][1], aa, b23);
        }
    }
}
__device__ __forceinline__ void g64_nn(const float* A, const float* B,
                                       ULL acc[4][2], int r0, int c0){
    #pragma unroll 4
    for (int k = 0; k < 64; k++){
        ULL b01 = pk2(B[k*PT+c0+0], B[k*PT+c0+1]);
        ULL b23 = pk2(B[k*PT+c0+2], B[k*PT+c0+3]);
        #pragma unroll
        for (int i = 0; i < 4; i++){
            float a = A[(r0+i)*PT+k];
            ULL aa = pk2(a, a);
            fma2(acc[i][0], aa, b01);
            fma2(acc[i][1], aa, b23);
        }
    }
}

// -------------- Phase A step j: diag factor + tri-inverse + panel (one CTA/matrix) --------
__global__ void __launch_bounds__(256) diagpanel_k(int j){
    extern __shared__ float sm[];
    float* sA = sm;
    float* sB = sm + 64*PT;
    float* sC = sm + 2*64*PT;
    int mat = blockIdx.x;
    float* M = g_M + (size_t)mat*FF*FF;
    float* W = g_W + (size_t)mat*FF*FF;
    int tid = threadIdx.x, tx = tid & 15, ty = tid >> 4;
    int r0 = ty*4, c0 = tx*4;

    ldt(sA, M + (size_t)(j*64)*FF + j*64, tid);
    __syncthreads();
    // LDL^T elimination (1 barrier per column)
    for (int k = 0; k < 64; k++){
        float pinv = 1.0f / sA[k*PT+k];
        #pragma unroll 4
        for (int e = tid; e < 4096; e += 256){
            int r = e >> 6, cc = e & 63;
            if (r > k && cc > k && cc <= r)
                sA[r*PT+cc] -= sA[r*PT+k]*sA[cc*PT+k]*pinv;
        }
        __syncthreads();
    }
    // rescale to Cholesky L
    if (tid < 64) sC[tid] = rsqrtf(sA[tid*PT+tid]);
    __syncthreads();
    #pragma unroll 4
    for (int e = tid; e < 4096; e += 256){
        int r = e >> 6, cc = e & 63;
        if (cc <= r) sA[r*PT+cc] *= sC[cc];
    }
    __syncthreads();

    // triangular inverse of L_jj -> sB (4 lanes per column)
    #pragma unroll 4
    for (int e = tid; e < 4096; e += 256) sB[(e>>6)*PT + (e&63)] = 0.0f;
    __syncthreads();
    {
        int c = tid >> 2, s = tid & 3;
        unsigned gmask = 0xFu << ((tid & 31) & ~3);
        float dv = 1.0f / sA[c*PT+c];
        if (s == 0) sB[c*PT+c] = dv;
        __syncwarp(gmask);
        for (int r = c+1; r < 64; r++){
            float part = 0.0f;
            for (int k2 = c + s; k2 < r; k2 += 4)
                part += sA[r*PT+k2] * sB[k2*PT+c];
            part += __shfl_xor_sync(gmask, part, 1);
            part += __shfl_xor_sync(gmask, part, 2);
            if (s == 0) sB[r*PT+c] = -part / sA[r*PT+r];
            __syncwarp(gmask);
        }
    }
    __syncthreads();
    // store Linv_jj into W
    #pragma unroll 4
    for (int e = tid; e < 4096; e += 256){
        int r = e >> 6, cc = e & 63;
        W[(size_t)(j*64 + r)*FF + j*64 + cc] = sB[r*PT+cc];
    }
    // panel: L_ij = A_ij * Linv_jj^T
    for (int i = j+1; i < 8; i++){
        __syncthreads();
        ldt(sC, M + (size_t)(i*64)*FF + j*64, tid);
        __syncthreads();
        ULL acc[4][2] = {};
        g64_nt(sC, sB, acc, r0, c0);
        #pragma unroll
        for (int ii = 0; ii < 4; ii++){
            float v0,v1,v2,v3;
            up2(acc[ii][0], v0, v1);
            up2(acc[ii][1], v2, v3);
            float4 v = {v0,v1,v2,v3};
            *(float4*)&M[(size_t)(i*64 + r0 + ii)*FF + j*64 + c0] = v;
        }
    }
}

// -------------- Phase A step j trailing: one CTA per (matrix, i>=kk>j tile) --------------
__global__ void __launch_bounds__(256) trailing_k(int j){
    extern __shared__ float sm[];
    float* sA = sm;               // L_ij
    float* sB = sm + 64*PT;       // L_kkj
    int mat = blockIdx.y;
    int t = blockIdx.x;
    // decode t -> (i, kk), i=j+1..7, kk=j+1..i
    int i = j+1, cnt = 1;
    while (t >= cnt){ t -= cnt; i++; cnt = i - j; }
    int kk = j+1 + t;
    float* M = g_M + (size_t)mat*FF*FF;
    int tid = threadIdx.x, tx = tid & 15, ty = tid >> 4;
    int r0 = ty*4, c0 = tx*4;
    ldt(sA, M + (size_t)(i*64)*FF + j*64, tid);
    ldt(sB, M + (size_t)(kk*64)*FF + j*64, tid);
    __syncthreads();
    ULL acc[4][2] = {};
    g64_nt(sA, sB, acc, r0, c0);
    #pragma unroll
    for (int ii = 0; ii < 4; ii++){
        float v0,v1,v2,v3;
        up2(acc[ii][0], v0, v1);
        up2(acc[ii][1], v2, v3);
        float4* dst = (float4*)&M[(size_t)(i*64 + r0 + ii)*FF + kk*64 + c0];
        float4 v = *dst;
        v.x -= v0; v.y -= v1; v.z -= v2; v.w -= v3;
        *dst = v;
    }
}

// -------------- Phase B: one CTA per (matrix, column j): W_ij chain down column ----------
__global__ void __launch_bounds__(256) phaseB_k(){
    extern __shared__ float sm[];
    float* sA = sm;
    float* sB = sm + 64*PT;
    float* sC = sm + 2*64*PT;
    int j   = blockIdx.x;         // 0..6 (heavy columns first)
    int mat = blockIdx.y;
    float* M = g_M + (size_t)mat*FF*FF;
    float* W = g_W + (size_t)mat*FF*FF;
    int tid = threadIdx.x, tx = tid & 15, ty = tid >> 4;
    int r0 = ty*4, c0 = tx*4;

    for (int i = j+1; i < 8; i++){
        ULL acc[4][2] = {};
        for (int k = j; k < i; k++){
            __syncthreads();
            ldt(sA, M + (size_t)(i*64)*FF + k*64, tid);   // L_ik
            ldt(sB, W + (size_t)(k*64)*FF + j*64, tid);   // W_kj
            __syncthreads();
            g64_nn(sA, sB, acc, r0, c0);
        }
        __syncthreads();
        #pragma unroll
        for (int ii = 0; ii < 4; ii++){
            float v0,v1,v2,v3;
            up2(acc[ii][0], v0, v1);
            up2(acc[ii][1], v2, v3);
            sC[(r0+ii)*PT + c0 + 0] = v0;
            sC[(r0+ii)*PT + c0 + 1] = v1;
            sC[(r0+ii)*PT + c0 + 2] = v2;
            sC[(r0+ii)*PT + c0 + 3] = v3;
        }
        ldt(sA, W + (size_t)(i*64)*FF + i*64, tid);       // Linv_ii
        __syncthreads();
        ULL acc2[4][2] = {};
        g64_nn(sA, sC, acc2, r0, c0);
        #pragma unroll
        for (int ii = 0; ii < 4; ii++){
            float v0,v1,v2,v3;
            up2(acc2[ii][0], v0, v1);
            up2(acc2[ii][1], v2, v3);
            float4 v = {-v0,-v1,-v2,-v3};
            *(float4*)&W[(size_t)(i*64 + r0 + ii)*FF + j*64 + c0] = v;
        }
        __syncthreads();
    }
}

// ------------------------- quad: ||W (mu - x)||^2 -------------------------
#define DP 130
__global__ void __launch_bounds__(256, 2) quad_k(const float* __restrict__ qf){
    extern __shared__ char smq[];
    ULL*   sW2 = (ULL*)smq;                          // 128*65 ULL
    float* sD  = (float*)(smq + 128*65*8);           // 64*130 f
    float* red = sD + 64*DP;                         // 16*128 f
    int pc = blockIdx.y;
    int p = pc / CC, c = pc % CC;
    int qbase = blockIdx.x * 128;
    int tid = threadIdx.x, tx = tid & 15, ty = tid >> 4;
    const float* Wg = g_W + (size_t)pc*FF*FF;
    const float* mu = g_means + (size_t)pc*FF;
    const float* xq = qf + ((size_t)p*QQ + qbase)*FF;
    ULL qs[4] = {0,0,0,0};

    for (int rb = 0; rb < 4; rb++){
        ULL acc[8][4];
        #pragma unroll
        for (int i = 0; i < 8; i++)
            #pragma unroll
            for (int j = 0; j < 4; j++) acc[i][j] = 0ULL;
        int nkt = 2*rb + 2;
        for (int kt = 0; kt < nkt; kt++){
            int k0 = kt*64;
            __syncthreads();
            #pragma unroll 4
            for (int idx = tid; idx < 128*64; idx += 256){
                int r = idx >> 6, k = idx & 63;
                float v = Wg[(size_t)(rb*128 + r)*FF + k0 + k];
                sW2[r*65 + k] = pk2(v, v);
            }
            #pragma unroll 4
            for (int idx = tid; idx < 128*64; idx += 256){
                int q = idx >> 6, k = idx & 63;
                sD[k*DP + q] = mu[k0+k] - xq[(size_t)q*FF + k0 + k];
            }
            __syncthreads();
            #pragma unroll 4
            for (int k = 0; k < 64; k++){
                ULL d[4];
                #pragma unroll
                for (int j = 0; j < 4; j++)
                    d[j] = *(const ULL*)&sD[k*DP + j*32 + tx*2];
                #pragma unroll
                for (int i = 0; i < 8; i++){
                    ULL w2 = sW2[(ty*8 + i)*65 + k];
                    #pragma unroll
                    for (int j = 0; j < 4; j++) fma2(acc[i][j], w2, d[j]);
                }
            }
        }
        #pragma unroll
        for (int i = 0; i < 8; i++)
            #pragma unroll
            for (int j = 0; j < 4; j++) fma2(qs[j], acc[i][j], acc[i][j]);
    }

    __syncthreads();
    #pragma unroll
    for (int j = 0; j < 4; j++){
        float lo, hi;
        up2(qs[j], lo, hi);
        red[ty*128 + j*32 + tx*2]     = lo;
        red[ty*128 + j*32 + tx*2 + 1] = hi;
    }
    __syncthreads();
    for (int s = 8; s; s >>= 1){
        if (ty < s){
            #pragma unroll
            for (int j = 0; j < 4; j++){
                int q = j*32 + tx*2;
                red[ty*128+q]   += red[(ty+s)*128+q];
                red[ty*128+q+1] += red[(ty+s)*128+q+1];
            }
        }
        __syncthreads();
    }
    if (tid < 128)
        g_quad[((size_t)p*QQ + qbase + tid)*CC + c] = red[tid];
}

// ------------------------- final outputs -------------------------
__global__ void logits_k(float* out){
    int q = blockIdx.x;
    int c = threadIdx.x;
    if (c < CC){
        float s = 0.0f;
        #pragma unroll
        for (int p = 0; p < PP; p++) s += g_quad[((size_t)p*QQ + q)*CC + c];
        out[q*CC + c] = -s * (1.0f/PP);
    }
}
__global__ void copymeans_k(float* out){
    for (int i = blockIdx.x*blockDim.x + threadIdx.x; i < NM*FF; i += gridDim.x*blockDim.x)
        out[QQ*CC + i] = g_means[i];
}

// ------------------------- launch -------------------------
extern "C" void kernel_launch(void* const* d_in, const int* in_sizes, int n_in,
                              void* d_out, int out_size) {
    const float* sf  = (const float*)d_in[0];
    const int*   lab = (const int*)d_in[1];
    const float* qf  = (const float*)d_in[2];
    float* out = (float*)d_out;

    const int CHOL_SMEM = 3*64*PT*(int)sizeof(float);               // 49920
    const int TR_SMEM   = 2*64*PT*(int)sizeof(float);               // 33280
    const int QUAD_SMEM = 128*65*8 + 64*DP*4 + 16*128*4;            // 108032
    cudaFuncSetAttribute(diagpanel_k, cudaFuncAttributeMaxDynamicSharedMemorySize, CHOL_SMEM);
    cudaFuncSetAttribute(phaseB_k,    cudaFuncAttributeMaxDynamicSharedMemorySize, CHOL_SMEM);
    cudaFuncSetAttribute(quad_k,      cudaFuncAttributeMaxDynamicSharedMemorySize, QUAD_SMEM);

    setup_k<<<1, 32>>>(lab);
    means_k<<<NM, 256>>>(sf);
    tm_k<<<PP, 256>>>(sf);
    taskcov_k<<<dim3(36, PP), 256>>>(sf);
    buildM_k<<<dim3(36, NM), 256>>>(sf);
    zeroWu_k<<<dim3(4, NM), 256>>>();
    for (int j = 0; j < 8; j++){
        diagpanel_k<<<NM, 256, CHOL_SMEM>>>(j);
        int nt = (7-j)*(8-j)/2;
        if (nt > 0)
            trailing_k<<<dim3(nt, NM), 256, TR_SMEM>>>(j);
    }
    phaseB_k<<<dim3(7, NM), 256, CHOL_SMEM>>>();
    quad_k<<<dim3(8, NM), 256, QUAD_SMEM>>>(qf);
    logits_k<<<QQ, 32>>>(out);
    if (out_size >= QQ*CC + NM*FF)
        copymeans_k<<<160, 512>>>(out);
}

// round 6
// speedup vs baseline: 1.3655x; 1.2556x over previous
#include <cuda_runtime.h>
#include <cuda_bf16.h>
#include <math.h>
#include <stdint.h>

#define PP 8
#define TT 200
#define FF 512
#define CC 20
#define QQ 1024
#define NM (PP*CC)
typedef unsigned long long ULL;

// ------------------------- device scratch -------------------------
__device__ float g_means[NM*FF];
__device__ float g_tm[PP*FF];
__device__ float g_task[(size_t)PP*FF*FF];
__device__ float g_M[(size_t)NM*FF*FF];            // cov_reg -> L (in place)
__device__ float g_W[(size_t)NM*FF*FF];            // W = L^{-1}
__device__ float g_quad[(size_t)PP*QQ*CC];
__device__ float g_Ymu[NM*FF];                     // y = W * mu (fp32 exact)
__device__ uint32_t g_Whi[(size_t)NM*FF*(FF/2)];   // bf16 pairs along k
__device__ uint32_t g_Wlo[(size_t)NM*FF*(FF/2)];
__device__ uint32_t g_Xhi[(size_t)PP*(FF/2)*QQ];   // [p][kp][q] bf16 pairs along k
__device__ uint32_t g_Xlo[(size_t)PP*(FF/2)*QQ];
__device__ int   g_members[CC*TT];
__device__ int   g_cnt[CC];
__device__ float g_icnts[CC], g_sclS[CC], g_sclT[CC];

// ------------------------- f32x2 helpers (cov/chol kernels) -------------------------
__device__ __forceinline__ ULL pk2(float lo, float hi){
    ULL r; asm("mov.b64 %0, {%1,%2};" : "=l"(r) : "f"(lo), "f"(hi)); return r;
}
__device__ __forceinline__ void up2(ULL v, float &a, float &b){
    asm("mov.b64 {%0,%1}, %2;" : "=f"(a), "=f"(b) : "l"(v));
}
__device__ __forceinline__ void fma2(ULL &d, ULL a, ULL b){
    asm("fma.rn.f32x2 %0, %1, %2, %0;" : "+l"(d) : "l"(a), "l"(b));
}

// ------------------------- bf16 split helper -------------------------
__device__ __forceinline__ void split2(float x0, float x1, uint32_t &hi, uint32_t &lo){
    __nv_bfloat16 h0 = __float2bfloat16(x0);
    __nv_bfloat16 h1 = __float2bfloat16(x1);
    float r0 = x0 - __bfloat162float(h0);
    float r1 = x1 - __bfloat162float(h1);
    __nv_bfloat16 l0 = __float2bfloat16(r0);
    __nv_bfloat16 l1 = __float2bfloat16(r1);
    hi = (uint32_t)__bfloat16_as_ushort(h0) | ((uint32_t)__bfloat16_as_ushort(h1) << 16);
    lo = (uint32_t)__bfloat16_as_ushort(l0) | ((uint32_t)__bfloat16_as_ushort(l1) << 16);
}

#define MMA_BF16(c, a0,a1,a2,a3, b0,b1) \
    asm volatile("mma.sync.aligned.m16n8k16.row.col.f32.bf16.bf16.f32 " \
        "{%0,%1,%2,%3},{%4,%5,%6,%7},{%8,%9},{%0,%1,%2,%3};" \
        : "+f"(c[0]),"+f"(c[1]),"+f"(c[2]),"+f"(c[3]) \
        : "r"(a0),"r"(a1),"r"(a2),"r"(a3),"r"(b0),"r"(b1))

// ------------------------- setup -------------------------
__global__ void setup_k(const int* __restrict__ lab_raw){
    if (threadIdx.x == 0 && blockIdx.x == 0){
        bool odd_all_zero = true;
        for (int t = 1; t < 200; t += 2) if (lab_raw[t] != 0) odd_all_zero = false;
        bool even_has_big = false;
        for (int t = 0; t < 200; t += 2) if (lab_raw[t] > 0) even_has_big = true;
        bool is64 = odd_all_zero && even_has_big;

        int cnt[CC];
        #pragma unroll
        for (int c = 0; c < CC; c++) cnt[c] = 0;
        for (int t = 0; t < TT; t++){
            int cc = is64 ? lab_raw[2*t] : lab_raw[t];
            if (cc < 0) cc = 0; if (cc >= CC) cc = CC-1;
            g_members[cc*TT + cnt[cc]] = t;
            cnt[cc]++;
        }
        for (int c = 0; c < CC; c++){
            g_cnt[c] = cnt[c];
            float cs  = fmaxf((float)cnt[c], 1.0f);
            g_icnts[c] = 1.0f / cs;
            float lam = cs / (cs + 1.0f);
            g_sclS[c] = lam / fmaxf((float)cnt[c] - 1.0f, 1.0f);
            g_sclT[c] = 1.0f - lam;
        }
    }
}

// ------------------------- class means -------------------------
__global__ void means_k(const float* __restrict__ sf){
    int pc = blockIdx.x;
    int p = pc / CC, c = pc % CC;
    int n = g_cnt[c];
    float ic = g_icnts[c];
    for (int f = threadIdx.x; f < FF; f += blockDim.x){
        float s = 0.0f;
        for (int m = 0; m < n; m++){
            int t = g_members[c*TT + m];
            s += sf[((size_t)p*TT + t)*FF + f];
        }
        g_means[(size_t)pc*FF + f] = s * ic;
    }
}

// ------------------------- task mean -------------------------
__global__ void tm_k(const float* __restrict__ sf){
    int p = blockIdx.x;
    for (int f = threadIdx.x; f < FF; f += blockDim.x){
        float s = 0.0f;
        for (int t = 0; t < TT; t++) s += sf[((size_t)p*TT + t)*FF + f];
        g_tm[p*FF + f] = s * (1.0f/TT);
    }
}

// ------------------------- task covariance -------------------------
__global__ void taskcov_k(const float* __restrict__ sf){
    int tile = blockIdx.x;          // 0..35 (tg<=tf)
    int p    = blockIdx.y;
    int tf = 0, rem = tile;
    while (rem >= tf+1){ rem -= tf+1; tf++; }
    int tg = rem;
    __shared__ float af[8][68], ag[8][68];
    int tid = threadIdx.x, tx = tid & 15, ty = tid >> 4;
    int r0 = ty*4, c0 = tx*4;
    float acc[4][4] = {};
    const float* tmv = g_tm + p*FF;
    for (int t0 = 0; t0 < TT; t0 += 8){
        __syncthreads();
        #pragma unroll
        for (int ii = 0; ii < 2; ii++){
            int idx = ii*256 + tid;
            int s = idx >> 6, f = idx & 63;
            const float* row = sf + ((size_t)p*TT + t0 + s)*FF;
            af[s][f] = row[tf*64 + f] - tmv[tf*64 + f];
            ag[s][f] = row[tg*64 + f] - tmv[tg*64 + f];
        }
        __syncthreads();
        #pragma unroll
        for (int s = 0; s < 8; s++){
            float a[4], b[4];
            #pragma unroll
            for (int i = 0; i < 4; i++) a[i] = af[s][r0+i];
            #pragma unroll
            for (int j = 0; j < 4; j++) b[j] = ag[s][c0+j];
            #pragma unroll
            for (int i = 0; i < 4; i++)
                #pragma unroll
                for (int j = 0; j < 4; j++) acc[i][j] += a[i]*b[j];
        }
    }
    const float inv = 1.0f/(TT-1);
    float* dst = g_task + (size_t)p*FF*FF;
    #pragma unroll
    for (int i = 0; i < 4; i++)
        #pragma unroll
        for (int j = 0; j < 4; j++){
            int fr = tf*64 + r0 + i, gc = tg*64 + c0 + j;
            float v = acc[i][j]*inv;
            dst[(size_t)fr*FF + gc] = v;
            dst[(size_t)gc*FF + fr] = v;
        }
}

// ------------------------- cov_reg -------------------------
__global__ void buildM_k(const float* __restrict__ sf){
    int tile = blockIdx.x;          // 0..35
    int pc   = blockIdx.y;
    int p = pc / CC, c = pc % CC;
    int tf = 0, rem = tile;
    while (rem >= tf+1){ rem -= tf+1; tf++; }
    int tg = rem;
    __shared__ float af[4][68], ag[4][68];
    int tid = threadIdx.x, tx = tid & 15, ty = tid >> 4;
    int r0 = ty*4, c0 = tx*4;
    float acc[4][4] = {};
    int n = g_cnt[c];
    const float* mu = g_means + (size_t)pc*FF;
    for (int m0 = 0; m0 < n; m0 += 4){
        __syncthreads();
        {
            int s = tid >> 6, f = tid & 63;
            int m = m0 + s;
            float va = 0.0f, vg = 0.0f;
            if (m < n){
                int t = g_members[c*TT + m];
                const float* row = sf + ((size_t)p*TT + t)*FF;
                va = row[tf*64 + f] - mu[tf*64 + f];
                vg = row[tg*64 + f] - mu[tg*64 + f];
            }
            af[s][f] = va; ag[s][f] = vg;
        }
        __syncthreads();
        #pragma unroll
        for (int s = 0; s < 4; s++){
            float a[4], b[4];
            #pragma unroll
            for (int i = 0; i < 4; i++) a[i] = af[s][r0+i];
            #pragma unroll
            for (int j = 0; j < 4; j++) b[j] = ag[s][c0+j];
            #pragma unroll
            for (int i = 0; i < 4; i++)
                #pragma unroll
                for (int j = 0; j < 4; j++) acc[i][j] += a[i]*b[j];
        }
    }
    float ss = g_sclS[c], st = g_sclT[c];
    float* dst = g_M + (size_t)pc*FF*FF;
    const float* tk = g_task + (size_t)p*FF*FF;
    #pragma unroll
    for (int i = 0; i < 4; i++)
        #pragma unroll
        for (int j = 0; j < 4; j++){
            int fr = tf*64 + r0 + i, gc = tg*64 + c0 + j;
            float v = ss*acc[i][j] + st*tk[(size_t)fr*FF + gc] + ((fr == gc) ? 1.0f : 0.0f);
            dst[(size_t)fr*FF + gc] = v;
            dst[(size_t)gc*FF + fr] = v;
        }
}

// -------- zero the above-64-diag blocks inside each 128-diag block --------
__global__ void zeroWu_k(){
    int rb  = blockIdx.x;
    int mat = blockIdx.y;
    float4 z = {0,0,0,0};
    for (int e = threadIdx.x; e < 64*16; e += 256){
        int r = e >> 4, c4 = e & 15;
        int row = rb*128 + r, col = rb*128 + 64 + c4*4;
        *(float4*)&g_W[(size_t)mat*FF*FF + (size_t)row*FF + col] = z;
    }
}

// ------------------------- 64x64 helpers (pitch 65) -------------------------
#define PT 65
__device__ __forceinline__ void ldt(float* dst, const float* g, int tid){
    #pragma unroll 4
    for (int e = tid; e < 4096; e += 256){
        int r = e >> 6, c = e & 63;
        dst[r*PT + c] = g[(size_t)r*FF + c];
    }
}
__device__ __forceinline__ void g64_nt(const float* A, const float* B,
                                       ULL acc[4][2], int r0, int c0){
    #pragma unroll 4
    for (int k = 0; k < 64; k++){
        ULL b01 = pk2(B[(c0+0)*PT+k], B[(c0+1)*PT+k]);
        ULL b23 = pk2(B[(c0+2)*PT+k], B[(c0+3)*PT+k]);
        #pragma unroll
        for (int i = 0; i < 4; i++){
            float a = A[(r0+i)*PT+k];
            ULL aa = pk2(a, a);
            fma2(acc[i][0], aa, b01);
            fma2(acc[i][1], aa, b23);
        }
    }
}
__device__ __forceinline__ void g64_nn(const float* A, const float* B,
                                       ULL acc[4][2], int r0, int c0){
    #pragma unroll 4
    for (int k = 0; k < 64; k++){
        ULL b01 = pk2(B[k*PT+c0+0], B[k*PT+c0+1]);
        ULL b23 = pk2(B[k*PT+c0+2], B[k*PT+c0+3]);
        #pragma unroll
        for (int i = 0; i < 4; i++){
            float a = A[(r0+i)*PT+k];
            ULL aa = pk2(a, a);
            fma2(acc[i][0], aa, b01);
            fma2(acc[i][1], aa, b23);
        }
    }
}

// -------------- Phase A step j: diag factor + tri-inverse + panel --------
__global__ void __launch_bounds__(256) diagpanel_k(int j){
    extern __shared__ float sm[];
    float* sA = sm;
    float* sB = sm + 64*PT;
    float* sC = sm + 2*64*PT;
    int mat = blockIdx.x;
    float* M = g_M + (size_t)mat*FF*FF;
    float* W = g_W + (size_t)mat*FF*FF;
    int tid = threadIdx.x, tx = tid & 15, ty = tid >> 4;
    int r0 = ty*4, c0 = tx*4;

    ldt(sA, M + (size_t)(j*64)*FF + j*64, tid);
    __syncthreads();
    for (int k = 0; k < 64; k++){
        float pinv = 1.0f / sA[k*PT+k];
        #pragma unroll 4
        for (int e = tid; e < 4096; e += 256){
            int r = e >> 6, cc = e & 63;
            if (r > k && cc > k && cc <= r)
                sA[r*PT+cc] -= sA[r*PT+k]*sA[cc*PT+k]*pinv;
        }
        __syncthreads();
    }
    if (tid < 64) sC[tid] = rsqrtf(sA[tid*PT+tid]);
    __syncthreads();
    #pragma unroll 4
    for (int e = tid; e < 4096; e += 256){
        int r = e >> 6, cc = e & 63;
        if (cc <= r) sA[r*PT+cc] *= sC[cc];
    }
    __syncthreads();

    #pragma unroll 4
    for (int e = tid; e < 4096; e += 256) sB[(e>>6)*PT + (e&63)] = 0.0f;
    __syncthreads();
    {
        int c = tid >> 2, s = tid & 3;
        unsigned gmask = 0xFu << ((tid & 31) & ~3);
        float dv = 1.0f / sA[c*PT+c];
        if (s == 0) sB[c*PT+c] = dv;
        __syncwarp(gmask);
        for (int r = c+1; r < 64; r++){
            float part = 0.0f;
            for (int k2 = c + s; k2 < r; k2 += 4)
                part += sA[r*PT+k2] * sB[k2*PT+c];
            part += __shfl_xor_sync(gmask, part, 1);
            part += __shfl_xor_sync(gmask, part, 2);
            if (s == 0) sB[r*PT+c] = -part / sA[r*PT+r];
            __syncwarp(gmask);
        }
    }
    __syncthreads();
    #pragma unroll 4
    for (int e = tid; e < 4096; e += 256){
        int r = e >> 6, cc = e & 63;
        W[(size_t)(j*64 + r)*FF + j*64 + cc] = sB[r*PT+cc];
    }
    for (int i = j+1; i < 8; i++){
        __syncthreads();
        ldt(sC, M + (size_t)(i*64)*FF + j*64, tid);
        __syncthreads();
        ULL acc[4][2] = {};
        g64_nt(sC, sB, acc, r0, c0);
        #pragma unroll
        for (int ii = 0; ii < 4; ii++){
            float v0,v1,v2,v3;
            up2(acc[ii][0], v0, v1);
            up2(acc[ii][1], v2, v3);
            float4 v = {v0,v1,v2,v3};
            *(float4*)&M[(size_t)(i*64 + r0 + ii)*FF + j*64 + c0] = v;
        }
    }
}

// -------------- Phase A trailing -------------
__global__ void __launch_bounds__(256) trailing_k(int j){
    extern __shared__ float sm[];
    float* sA = sm;
    float* sB = sm + 64*PT;
    int mat = blockIdx.y;
    int t = blockIdx.x;
    int i = j+1, cnt = 1;
    while (t >= cnt){ t -= cnt; i++; cnt = i - j; }
    int kk = j+1 + t;
    float* M = g_M + (size_t)mat*FF*FF;
    int tid = threadIdx.x, tx = tid & 15, ty = tid >> 4;
    int r0 = ty*4, c0 = tx*4;
    ldt(sA, M + (size_t)(i*64)*FF + j*64, tid);
    ldt(sB, M + (size_t)(kk*64)*FF + j*64, tid);
    __syncthreads();
    ULL acc[4][2] = {};
    g64_nt(sA, sB, acc, r0, c0);
    #pragma unroll
    for (int ii = 0; ii < 4; ii++){
        float v0,v1,v2,v3;
        up2(acc[ii][0], v0, v1);
        up2(acc[ii][1], v2, v3);
        float4* dst = (float4*)&M[(size_t)(i*64 + r0 + ii)*FF + kk*64 + c0];
        float4 v = *dst;
        v.x -= v0; v.y -= v1; v.z -= v2; v.w -= v3;
        *dst = v;
    }
}

// -------------- Phase B -------------
__global__ void __launch_bounds__(256) phaseB_k(){
    extern __shared__ float sm[];
    float* sA = sm;
    float* sB = sm + 64*PT;
    float* sC = sm + 2*64*PT;
    int j   = blockIdx.x;
    int mat = blockIdx.y;
    float* M = g_M + (size_t)mat*FF*FF;
    float* W = g_W + (size_t)mat*FF*FF;
    int tid = threadIdx.x, tx = tid & 15, ty = tid >> 4;
    int r0 = ty*4, c0 = tx*4;

    for (int i = j+1; i < 8; i++){
        ULL acc[4][2] = {};
        for (int k = j; k < i; k++){
            __syncthreads();
            ldt(sA, M + (size_t)(i*64)*FF + k*64, tid);
            ldt(sB, W + (size_t)(k*64)*FF + j*64, tid);
            __syncthreads();
            g64_nn(sA, sB, acc, r0, c0);
        }
        __syncthreads();
        #pragma unroll
        for (int ii = 0; ii < 4; ii++){
            float v0,v1,v2,v3;
            up2(acc[ii][0], v0, v1);
            up2(acc[ii][1], v2, v3);
            sC[(r0+ii)*PT + c0 + 0] = v0;
            sC[(r0+ii)*PT + c0 + 1] = v1;
            sC[(r0+ii)*PT + c0 + 2] = v2;
            sC[(r0+ii)*PT + c0 + 3] = v3;
        }
        ldt(sA, W + (size_t)(i*64)*FF + i*64, tid);
        __syncthreads();
        ULL acc2[4][2] = {};
        g64_nn(sA, sC, acc2, r0, c0);
        #pragma unroll
        for (int ii = 0; ii < 4; ii++){
            float v0,v1,v2,v3;
            up2(acc2[ii][0], v0, v1);
            up2(acc2[ii][1], v2, v3);
            float4 v = {-v0,-v1,-v2,-v3};
            *(float4*)&W[(size_t)(i*64 + r0 + ii)*FF + j*64 + c0] = v;
        }
        __syncthreads();
    }
}

// ------------------------- W split into bf16 hi/lo (pairs along k) -------------------------
__global__ void wsplit_k(){
    int pc = blockIdx.x;
    const float2* src = (const float2*)(g_W + (size_t)pc*FF*FF);
    uint32_t* dh = g_Whi + (size_t)pc*FF*(FF/2);
    uint32_t* dl = g_Wlo + (size_t)pc*FF*(FF/2);
    for (int u = threadIdx.x; u < FF*(FF/2); u += blockDim.x){
        float2 w = src[u];
        uint32_t hi, lo;
        split2(w.x, w.y, hi, lo);
        dh[u] = hi; dl[u] = lo;
    }
}

// ------------------------- queries split + transpose: [p][kp][q] -------------------------
__global__ void qsplit_k(const float* __restrict__ qf){
    __shared__ float sq[16][FF];
    int qb = blockIdx.x;           // 0..63 (16 queries each)
    int p  = blockIdx.y;
    int tid = threadIdx.x;
    for (int u = tid; u < 16*FF; u += 256){
        int qi = u / FF, f = u % FF;
        sq[qi][f] = qf[((size_t)p*QQ + qb*16 + qi)*FF + f];
    }
    __syncthreads();
    uint32_t* dh = g_Xhi + (size_t)p*(FF/2)*QQ;
    uint32_t* dl = g_Xlo + (size_t)p*(FF/2)*QQ;
    for (int u = tid; u < 256*16; u += 256){
        int kp = u >> 4, qi = u & 15;
        uint32_t hi, lo;
        split2(sq[qi][2*kp], sq[qi][2*kp+1], hi, lo);
        dh[(size_t)kp*QQ + qb*16 + qi] = hi;
        dl[(size_t)kp*QQ + qb*16 + qi] = lo;
    }
}

// ------------------------- y = W * mu (fp32 exact, coalesced) -------------------------
__global__ void ymu_k(){
    __shared__ float smu[FF];
    int pc = blockIdx.x;
    int tid = threadIdx.x, lane = tid & 31, wid = tid >> 5;
    const float* W = g_W + (size_t)pc*FF*FF;
    for (int f = tid; f < FF; f += 256) smu[f] = g_means[(size_t)pc*FF + f];
    __syncthreads();
    for (int r = wid; r < FF; r += 8){
        float s = 0.0f;
        for (int k = lane; k <= r; k += 32)
            s += W[(size_t)r*FF + k] * smu[k];
        #pragma unroll
        for (int o = 16; o; o >>= 1) s += __shfl_xor_sync(0xFFFFFFFFu, s, o);
        if (lane == 0) g_Ymu[pc*FF + r] = s;
    }
}

// ================= quad via mma.sync bf16x3: quad = || y - W x ||^2 =================
// Grid (8 qtiles, 160 pc), 256 threads (8 warps: 2 m x 4 n), 2 CTAs/SM.
// smem: sWhi/sWlo [128][36] u32, sXhi/sXlo [32][136] u32, red[128] f32.
#define WPITCH 36
#define XPITCH 136
#define QMMA_SMEM (2*128*WPITCH*4 + 2*32*XPITCH*4 + 128*4)
__global__ void __launch_bounds__(256, 2) quadmma_k(){
    extern __shared__ uint32_t smu32[];
    uint32_t* sWhi = smu32;
    uint32_t* sWlo = sWhi + 128*WPITCH;
    uint32_t* sXhi = sWlo + 128*WPITCH;
    uint32_t* sXlo = sXhi + 32*XPITCH;
    float*    red  = (float*)(sXlo + 32*XPITCH);
    int pc = blockIdx.y;
    int p = pc / CC, c = pc % CC;
    int qbase = blockIdx.x * 128;
    int tid = threadIdx.x, lane = tid & 31, wid = tid >> 5;
    int g = lane >> 2, t = lane & 3;
    int warpM = wid & 1, warpN = wid >> 1;
    const uint32_t* gwh = g_Whi + (size_t)pc*FF*(FF/2);
    const uint32_t* gwl = g_Wlo + (size_t)pc*FF*(FF/2);
    const uint32_t* gxh = g_Xhi + (size_t)p*(FF/2)*QQ + qbase;
    const uint32_t* gxl = g_Xlo + (size_t)p*(FF/2)*QQ + qbase;
    const float*    ym  = g_Ymu + pc*FF;

    if (tid < 128) red[tid] = 0.0f;
    float qs[8];
    #pragma unroll
    for (int j = 0; j < 8; j++) qs[j] = 0.0f;

    for (int rb = 0; rb < 4; rb++){
        float acc[4][4][4];
        #pragma unroll
        for (int mi = 0; mi < 4; mi++)
            #pragma unroll
            for (int ni = 0; ni < 4; ni++)
                #pragma unroll
                for (int r = 0; r < 4; r++) acc[mi][ni][r] = 0.0f;

        int nch = 2*rb + 2;
        for (int ch = 0; ch < nch; ch++){
            int kp0 = ch*32;
            __syncthreads();
            #pragma unroll 4
            for (int u = tid; u < 4096; u += 256){
                int r = u >> 5, kp = u & 31;
                size_t go = (size_t)(rb*128 + r)*(FF/2) + kp0 + kp;
                sWhi[r*WPITCH + kp] = gwh[go];
                sWlo[r*WPITCH + kp] = gwl[go];
            }
            #pragma unroll 4
            for (int u = tid; u < 4096; u += 256){
                int kp = u >> 7, q = u & 127;
                size_t go = (size_t)(kp0 + kp)*QQ + q;
                sXhi[kp*XPITCH + q] = gxh[go];
                sXlo[kp*XPITCH + q] = gxl[go];
            }
            __syncthreads();
            #pragma unroll
            for (int s = 0; s < 4; s++){
                uint32_t bh[4][2], bl[4][2];
                #pragma unroll
                for (int ni = 0; ni < 4; ni++){
                    int col = warpN*32 + ni*8 + g;
                    bh[ni][0] = sXhi[(8*s + t)*XPITCH + col];
                    bh[ni][1] = sXhi[(8*s + t + 4)*XPITCH + col];
                    bl[ni][0] = sXlo[(8*s + t)*XPITCH + col];
                    bl[ni][1] = sXlo[(8*s + t + 4)*XPITCH + col];
                }
                #pragma unroll
                for (int mi = 0; mi < 4; mi++){
                    int row = warpM*64 + mi*16 + g;
                    uint32_t ah0 = sWhi[row*WPITCH + 8*s + t];
                    uint32_t ah1 = sWhi[(row+8)*WPITCH + 8*s + t];
                    uint32_t ah2 = sWhi[row*WPITCH + 8*s + t + 4];
                    uint32_t ah3 = sWhi[(row+8)*WPITCH + 8*s + t + 4];
                    uint32_t al0 = sWlo[row*WPITCH + 8*s + t];
                    uint32_t al1 = sWlo[(row+8)*WPITCH + 8*s + t];
                    uint32_t al2 = sWlo[row*WPITCH + 8*s + t + 4];
                    uint32_t al3 = sWlo[(row+8)*WPITCH + 8*s + t + 4];
                    #pragma unroll
                    for (int ni = 0; ni < 4; ni++){
                        MMA_BF16(acc[mi][ni], ah0,ah1,ah2,ah3, bh[ni][0],bh[ni][1]);
                        MMA_BF16(acc[mi][ni], ah0,ah1,ah2,ah3, bl[ni][0],bl[ni][1]);
                        MMA_BF16(acc[mi][ni], al0,al1,al2,al3, bh[ni][0],bh[ni][1]);
                    }
                }
            }
        }
        // epilogue for this row block: qs += (y - z)^2
        #pragma unroll
        for (int mi = 0; mi < 4; mi++){
            int r1 = rb*128 + warpM*64 + mi*16 + g;
            float y1 = ym[r1], y2 = ym[r1 + 8];
            #pragma unroll
            for (int ni = 0; ni < 4; ni++){
                float d0 = y1 - acc[mi][ni][0];
                float d1 = y1 - acc[mi][ni][1];
                float d2 = y2 - acc[mi][ni][2];
                float d3 = y2 - acc[mi][ni][3];
                qs[2*ni]   += d0*d0 + d2*d2;
                qs[2*ni+1] += d1*d1 + d3*d3;
            }
        }
    }

    // reduce across g within warp
    #pragma unroll
    for (int j = 0; j < 8; j++)
        #pragma unroll
        for (int o = 4; o < 32; o <<= 1)
            qs[j] += __shfl_xor_sync(0xFFFFFFFFu, qs[j], o);
    if (lane < 4){
        #pragma unroll
        for (int j = 0; j < 8; j++){
            int ni = j >> 1, b = j & 1;
            int q = warpN*32 + ni*8 + 2*lane + b;
            atomicAdd(&red[q], qs[j]);
        }
    }
    __syncthreads();
    if (tid < 128)
        g_quad[((size_t)p*QQ + qbase + tid)*CC + c] = red[tid];
}

// ------------------------- final outputs -------------------------
__global__ void logits_k(float* out){
    int q = blockIdx.x;
    int c = threadIdx.x;
    if (c < CC){
        float s = 0.0f;
        #pragma unroll
        for (int p = 0; p < PP; p++) s += g_quad[((size_t)p*QQ + q)*CC + c];
        out[q*CC + c] = -s * (1.0f/PP);
    }
}
__global__ void copymeans_k(float* out){
    for (int i = blockIdx.x*blockDim.x + threadIdx.x; i < NM*FF; i += gridDim.x*blockDim.x)
        out[QQ*CC + i] = g_means[i];
}

// ------------------------- launch -------------------------
extern "C" void kernel_launch(void* const* d_in, const int* in_sizes, int n_in,
                              void* d_out, int out_size) {
    const float* sf  = (const float*)d_in[0];
    const int*   lab = (const int*)d_in[1];
    const float* qf  = (const float*)d_in[2];
    float* out = (float*)d_out;

    const int CHOL_SMEM = 3*64*PT*(int)sizeof(float);
    const int TR_SMEM   = 2*64*PT*(int)sizeof(float);
    cudaFuncSetAttribute(diagpanel_k, cudaFuncAttributeMaxDynamicSharedMemorySize, CHOL_SMEM);
    cudaFuncSetAttribute(phaseB_k,    cudaFuncAttributeMaxDynamicSharedMemorySize, CHOL_SMEM);
    cudaFuncSetAttribute(quadmma_k,   cudaFuncAttributeMaxDynamicSharedMemorySize, QMMA_SMEM);

    setup_k<<<1, 32>>>(lab);
    means_k<<<NM, 256>>>(sf);
    tm_k<<<PP, 256>>>(sf);
    qsplit_k<<<dim3(64, PP), 256>>>(qf);
    taskcov_k<<<dim3(36, PP), 256>>>(sf);
    buildM_k<<<dim3(36, NM), 256>>>(sf);
    zeroWu_k<<<dim3(4, NM), 256>>>();
    for (int j = 0; j < 8; j++){
        diagpanel_k<<<NM, 256, CHOL_SMEM>>>(j);
        int nt = (7-j)*(8-j)/2;
        if (nt > 0)
            trailing_k<<<dim3(nt, NM), 256, TR_SMEM>>>(j);
    }
    phaseB_k<<<dim3(7, NM), 256, CHOL_SMEM>>>();
    wsplit_k<<<NM, 256>>>();
    ymu_k<<<NM, 256>>>();
    quadmma_k<<<dim3(8, NM), 256, QMMA_SMEM>>>();
    logits_k<<<QQ, 32>>>(out);
    if (out_size >= QQ*CC + NM*FF)
        copymeans_k<<<160, 512>>>(out);
}

// round 7
// speedup vs baseline: 1.4966x; 1.0960x over previous
#include <cuda_runtime.h>
#include <cuda_bf16.h>
#include <math.h>
#include <stdint.h>

#define PP 8
#define TT 200
#define FF 512
#define CC 20
#define QQ 1024
#define NM (PP*CC)
typedef unsigned long long ULL;

// ------------------------- device scratch -------------------------
__device__ float g_means[NM*FF];
__device__ float g_tm[PP*FF];
__device__ float g_task[(size_t)PP*FF*FF];
__device__ float g_M[(size_t)NM*FF*FF];            // cov_reg -> L (in place)
__device__ float g_W[(size_t)NM*FF*FF];            // W = L^{-1}
__device__ float g_quad[(size_t)PP*QQ*CC];
__device__ float g_Ymu[NM*FF];                     // y = W * mu (fp32 exact)
__device__ uint32_t g_Whi[(size_t)NM*FF*(FF/2)];   // bf16 pairs along k
__device__ uint32_t g_Wlo[(size_t)NM*FF*(FF/2)];
__device__ uint32_t g_Xhi[(size_t)PP*(FF/2)*QQ];   // [p][kp][q]
__device__ uint32_t g_Xlo[(size_t)PP*(FF/2)*QQ];
__device__ int   g_members[CC*TT];
__device__ int   g_cnt[CC];
__device__ float g_icnts[CC], g_sclS[CC], g_sclT[CC];

// ------------------------- f32x2 helpers -------------------------
__device__ __forceinline__ ULL pk2(float lo, float hi){
    ULL r; asm("mov.b64 %0, {%1,%2};" : "=l"(r) : "f"(lo), "f"(hi)); return r;
}
__device__ __forceinline__ void up2(ULL v, float &a, float &b){
    asm("mov.b64 {%0,%1}, %2;" : "=f"(a), "=f"(b) : "l"(v));
}
__device__ __forceinline__ void fma2(ULL &d, ULL a, ULL b){
    asm("fma.rn.f32x2 %0, %1, %2, %0;" : "+l"(d) : "l"(a), "l"(b));
}

// ------------------------- bf16 split helper -------------------------
__device__ __forceinline__ void split2(float x0, float x1, uint32_t &hi, uint32_t &lo){
    __nv_bfloat16 h0 = __float2bfloat16(x0);
    __nv_bfloat16 h1 = __float2bfloat16(x1);
    float r0 = x0 - __bfloat162float(h0);
    float r1 = x1 - __bfloat162float(h1);
    __nv_bfloat16 l0 = __float2bfloat16(r0);
    __nv_bfloat16 l1 = __float2bfloat16(r1);
    hi = (uint32_t)__bfloat16_as_ushort(h0) | ((uint32_t)__bfloat16_as_ushort(h1) << 16);
    lo = (uint32_t)__bfloat16_as_ushort(l0) | ((uint32_t)__bfloat16_as_ushort(l1) << 16);
}

#define MMA_BF16(c, a0,a1,a2,a3, b0,b1) \
    asm volatile("mma.sync.aligned.m16n8k16.row.col.f32.bf16.bf16.f32 " \
        "{%0,%1,%2,%3},{%4,%5,%6,%7},{%8,%9},{%0,%1,%2,%3};" \
        : "+f"(c[0]),"+f"(c[1]),"+f"(c[2]),"+f"(c[3]) \
        : "r"(a0),"r"(a1),"r"(a2),"r"(a3),"r"(b0),"r"(b1))

// ------------------------- setup -------------------------
__global__ void setup_k(const int* __restrict__ lab_raw){
    if (threadIdx.x == 0 && blockIdx.x == 0){
        bool odd_all_zero = true;
        for (int t = 1; t < 200; t += 2) if (lab_raw[t] != 0) odd_all_zero = false;
        bool even_has_big = false;
        for (int t = 0; t < 200; t += 2) if (lab_raw[t] > 0) even_has_big = true;
        bool is64 = odd_all_zero && even_has_big;

        int cnt[CC];
        #pragma unroll
        for (int c = 0; c < CC; c++) cnt[c] = 0;
        for (int t = 0; t < TT; t++){
            int cc = is64 ? lab_raw[2*t] : lab_raw[t];
            if (cc < 0) cc = 0; if (cc >= CC) cc = CC-1;
            g_members[cc*TT + cnt[cc]] = t;
            cnt[cc]++;
        }
        for (int c = 0; c < CC; c++){
            g_cnt[c] = cnt[c];
            float cs  = fmaxf((float)cnt[c], 1.0f);
            g_icnts[c] = 1.0f / cs;
            float lam = cs / (cs + 1.0f);
            g_sclS[c] = lam / fmaxf((float)cnt[c] - 1.0f, 1.0f);
            g_sclT[c] = 1.0f - lam;
        }
    }
}

// ------------------------- class means -------------------------
__global__ void means_k(const float* __restrict__ sf){
    int pc = blockIdx.x;
    int p = pc / CC, c = pc % CC;
    int n = g_cnt[c];
    float ic = g_icnts[c];
    for (int f = threadIdx.x; f < FF; f += blockDim.x){
        float s = 0.0f;
        for (int m = 0; m < n; m++){
            int t = g_members[c*TT + m];
            s += sf[((size_t)p*TT + t)*FF + f];
        }
        g_means[(size_t)pc*FF + f] = s * ic;
    }
}

// ------------------------- task mean -------------------------
__global__ void tm_k(const float* __restrict__ sf){
    int p = blockIdx.x;
    for (int f = threadIdx.x; f < FF; f += blockDim.x){
        float s = 0.0f;
        for (int t = 0; t < TT; t++) s += sf[((size_t)p*TT + t)*FF + f];
        g_tm[p*FF + f] = s * (1.0f/TT);
    }
}

// ------------------------- task covariance -------------------------
__global__ void taskcov_k(const float* __restrict__ sf){
    int tile = blockIdx.x;          // 0..35 (tg<=tf)
    int p    = blockIdx.y;
    int tf = 0, rem = tile;
    while (rem >= tf+1){ rem -= tf+1; tf++; }
    int tg = rem;
    __shared__ float af[8][68], ag[8][68];
    int tid = threadIdx.x, tx = tid & 15, ty = tid >> 4;
    int r0 = ty*4, c0 = tx*4;
    float acc[4][4] = {};
    const float* tmv = g_tm + p*FF;
    for (int t0 = 0; t0 < TT; t0 += 8){
        __syncthreads();
        #pragma unroll
        for (int ii = 0; ii < 2; ii++){
            int idx = ii*256 + tid;
            int s = idx >> 6, f = idx & 63;
            const float* row = sf + ((size_t)p*TT + t0 + s)*FF;
            af[s][f] = row[tf*64 + f] - tmv[tf*64 + f];
            ag[s][f] = row[tg*64 + f] - tmv[tg*64 + f];
        }
        __syncthreads();
        #pragma unroll
        for (int s = 0; s < 8; s++){
            float a[4], b[4];
            #pragma unroll
            for (int i = 0; i < 4; i++) a[i] = af[s][r0+i];
            #pragma unroll
            for (int j = 0; j < 4; j++) b[j] = ag[s][c0+j];
            #pragma unroll
            for (int i = 0; i < 4; i++)
                #pragma unroll
                for (int j = 0; j < 4; j++) acc[i][j] += a[i]*b[j];
        }
    }
    const float inv = 1.0f/(TT-1);
    float* dst = g_task + (size_t)p*FF*FF;
    #pragma unroll
    for (int i = 0; i < 4; i++)
        #pragma unroll
        for (int j = 0; j < 4; j++){
            int fr = tf*64 + r0 + i, gc = tg*64 + c0 + j;
            float v = acc[i][j]*inv;
            dst[(size_t)fr*FF + gc] = v;
            dst[(size_t)gc*FF + fr] = v;
        }
}

// ------------------------- cov_reg -------------------------
__global__ void buildM_k(const float* __restrict__ sf){
    int tile = blockIdx.x;          // 0..35
    int pc   = blockIdx.y;
    int p = pc / CC, c = pc % CC;
    int tf = 0, rem = tile;
    while (rem >= tf+1){ rem -= tf+1; tf++; }
    int tg = rem;
    __shared__ float af[4][68], ag[4][68];
    int tid = threadIdx.x, tx = tid & 15, ty = tid >> 4;
    int r0 = ty*4, c0 = tx*4;
    float acc[4][4] = {};
    int n = g_cnt[c];
    const float* mu = g_means + (size_t)pc*FF;
    for (int m0 = 0; m0 < n; m0 += 4){
        __syncthreads();
        {
            int s = tid >> 6, f = tid & 63;
            int m = m0 + s;
            float va = 0.0f, vg = 0.0f;
            if (m < n){
                int t = g_members[c*TT + m];
                const float* row = sf + ((size_t)p*TT + t)*FF;
                va = row[tf*64 + f] - mu[tf*64 + f];
                vg = row[tg*64 + f] - mu[tg*64 + f];
            }
            af[s][f] = va; ag[s][f] = vg;
        }
        __syncthreads();
        #pragma unroll
        for (int s = 0; s < 4; s++){
            float a[4], b[4];
            #pragma unroll
            for (int i = 0; i < 4; i++) a[i] = af[s][r0+i];
            #pragma unroll
            for (int j = 0; j < 4; j++) b[j] = ag[s][c0+j];
            #pragma unroll
            for (int i = 0; i < 4; i++)
                #pragma unroll
                for (int j = 0; j < 4; j++) acc[i][j] += a[i]*b[j];
        }
    }
    float ss = g_sclS[c], st = g_sclT[c];
    float* dst = g_M + (size_t)pc*FF*FF;
    const float* tk = g_task + (size_t)p*FF*FF;
    #pragma unroll
    for (int i = 0; i < 4; i++)
        #pragma unroll
        for (int j = 0; j < 4; j++){
            int fr = tf*64 + r0 + i, gc = tg*64 + c0 + j;
            float v = ss*acc[i][j] + st*tk[(size_t)fr*FF + gc] + ((fr == gc) ? 1.0f : 0.0f);
            dst[(size_t)fr*FF + gc] = v;
            dst[(size_t)gc*FF + fr] = v;
        }
}

// -------- zero split arrays in the upper-right 64x64 of each 128-diag block --------
__global__ void zeroWu_k(){
    int rb  = blockIdx.x;
    int mat = blockIdx.y;
    uint32_t* wh = g_Whi + (size_t)mat*FF*(FF/2);
    uint32_t* wl = g_Wlo + (size_t)mat*FF*(FF/2);
    for (int e = threadIdx.x; e < 64*32; e += 256){
        int r = e >> 5, cp = e & 31;
        size_t o = (size_t)(rb*128 + r)*(FF/2) + rb*64 + 32 + cp;
        wh[o] = 0u; wl[o] = 0u;
    }
}

// -------- zero g_quad (accumulated via atomics) --------
__global__ void zeroquad_k(){
    size_t n = (size_t)PP*QQ*CC;
    for (size_t i = (size_t)blockIdx.x*blockDim.x + threadIdx.x; i < n;
         i += (size_t)gridDim.x*blockDim.x)
        g_quad[i] = 0.0f;
}

// ------------------------- 64x64 helpers (pitch 65) -------------------------
#define PT 65
__device__ __forceinline__ void ldt(float* dst, const float* g, int tid){
    #pragma unroll 4
    for (int e = tid; e < 4096; e += 256){
        int r = e >> 6, c = e & 63;
        dst[r*PT + c] = g[(size_t)r*FF + c];
    }
}
__device__ __forceinline__ void g64_nt(const float* A, const float* B,
                                       ULL acc[4][2], int r0, int c0){
    #pragma unroll 4
    for (int k = 0; k < 64; k++){
        ULL b01 = pk2(B[(c0+0)*PT+k], B[(c0+1)*PT+k]);
        ULL b23 = pk2(B[(c0+2)*PT+k], B[(c0+3)*PT+k]);
        #pragma unroll
        for (int i = 0; i < 4; i++){
            float a = A[(r0+i)*PT+k];
            ULL aa = pk2(a, a);
            fma2(acc[i][0], aa, b01);
            fma2(acc[i][1], aa, b23);
        }
    }
}
__device__ __forceinline__ void g64_nn(const float* A, const float* B,
                                       ULL acc[4][2], int r0, int c0){
    #pragma unroll 4
    for (int k = 0; k < 64; k++){
        ULL b01 = pk2(B[k*PT+c0+0], B[k*PT+c0+1]);
        ULL b23 = pk2(B[k*PT+c0+2], B[k*PT+c0+3]);
        #pragma unroll
        for (int i = 0; i < 4; i++){
            float a = A[(r0+i)*PT+k];
            ULL aa = pk2(a, a);
            fma2(acc[i][0], aa, b01);
            fma2(acc[i][1], aa, b23);
        }
    }
}

// -------------- Phase A step j: diag factor + tri-inverse + panel --------
__global__ void __launch_bounds__(256) diagpanel_k(int j){
    extern __shared__ float sm[];
    float* sA = sm;
    float* sB = sm + 64*PT;
    float* sC = sm + 2*64*PT;
    int mat = blockIdx.x;
    float* M = g_M + (size_t)mat*FF*FF;
    float* W = g_W + (size_t)mat*FF*FF;
    int tid = threadIdx.x, tx = tid & 15, ty = tid >> 4;
    int r0 = ty*4, c0 = tx*4;

    ldt(sA, M + (size_t)(j*64)*FF + j*64, tid);
    __syncthreads();
    for (int k = 0; k < 64; k++){
        float pinv = 1.0f / sA[k*PT+k];
        #pragma unroll 4
        for (int e = tid; e < 4096; e += 256){
            int r = e >> 6, cc = e & 63;
            if (r > k && cc > k && cc <= r)
                sA[r*PT+cc] -= sA[r*PT+k]*sA[cc*PT+k]*pinv;
        }
        __syncthreads();
    }
    if (tid < 64) sC[tid] = rsqrtf(sA[tid*PT+tid]);
    __syncthreads();
    #pragma unroll 4
    for (int e = tid; e < 4096; e += 256){
        int r = e >> 6, cc = e & 63;
        if (cc <= r) sA[r*PT+cc] *= sC[cc];
    }
    __syncthreads();

    #pragma unroll 4
    for (int e = tid; e < 4096; e += 256) sB[(e>>6)*PT + (e&63)] = 0.0f;
    __syncthreads();
    {
        int c = tid >> 2, s = tid & 3;
        unsigned gmask = 0xFu << ((tid & 31) & ~3);
        float dv = 1.0f / sA[c*PT+c];
        if (s == 0) sB[c*PT+c] = dv;
        __syncwarp(gmask);
        for (int r = c+1; r < 64; r++){
            float part = 0.0f;
            for (int k2 = c + s; k2 < r; k2 += 4)
                part += sA[r*PT+k2] * sB[k2*PT+c];
            part += __shfl_xor_sync(gmask, part, 1);
            part += __shfl_xor_sync(gmask, part, 2);
            if (s == 0) sB[r*PT+c] = -part / sA[r*PT+r];
            __syncwarp(gmask);
        }
    }
    __syncthreads();
    // store Linv_jj into W (fp32) + split (bf16 hi/lo)
    #pragma unroll 4
    for (int e = tid; e < 4096; e += 256){
        int r = e >> 6, cc = e & 63;
        W[(size_t)(j*64 + r)*FF + j*64 + cc] = sB[r*PT+cc];
    }
    {
        uint32_t* wh = g_Whi + (size_t)mat*FF*(FF/2);
        uint32_t* wl = g_Wlo + (size_t)mat*FF*(FF/2);
        for (int e = tid; e < 2048; e += 256){
            int r = e >> 5, cp = e & 31;
            uint32_t hi, lo;
            split2(sB[r*PT + 2*cp], sB[r*PT + 2*cp + 1], hi, lo);
            size_t o = (size_t)(j*64 + r)*(FF/2) + j*32 + cp;
            wh[o] = hi; wl[o] = lo;
        }
    }
    for (int i = j+1; i < 8; i++){
        __syncthreads();
        ldt(sC, M + (size_t)(i*64)*FF + j*64, tid);
        __syncthreads();
        ULL acc[4][2] = {};
        g64_nt(sC, sB, acc, r0, c0);
        #pragma unroll
        for (int ii = 0; ii < 4; ii++){
            float v0,v1,v2,v3;
            up2(acc[ii][0], v0, v1);
            up2(acc[ii][1], v2, v3);
            float4 v = {v0,v1,v2,v3};
            *(float4*)&M[(size_t)(i*64 + r0 + ii)*FF + j*64 + c0] = v;
        }
    }
}

// -------------- Phase A trailing -------------
__global__ void __launch_bounds__(256) trailing_k(int j){
    extern __shared__ float sm[];
    float* sA = sm;
    float* sB = sm + 64*PT;
    int mat = blockIdx.y;
    int t = blockIdx.x;
    int i = j+1, cnt = 1;
    while (t >= cnt){ t -= cnt; i++; cnt = i - j; }
    int kk = j+1 + t;
    float* M = g_M + (size_t)mat*FF*FF;
    int tid = threadIdx.x, tx = tid & 15, ty = tid >> 4;
    int r0 = ty*4, c0 = tx*4;
    ldt(sA, M + (size_t)(i*64)*FF + j*64, tid);
    ldt(sB, M + (size_t)(kk*64)*FF + j*64, tid);
    __syncthreads();
    ULL acc[4][2] = {};
    g64_nt(sA, sB, acc, r0, c0);
    #pragma unroll
    for (int ii = 0; ii < 4; ii++){
        float v0,v1,v2,v3;
        up2(acc[ii][0], v0, v1);
        up2(acc[ii][1], v2, v3);
        float4* dst = (float4*)&M[(size_t)(i*64 + r0 + ii)*FF + kk*64 + c0];
        float4 v = *dst;
        v.x -= v0; v.y -= v1; v.z -= v2; v.w -= v3;
        *dst = v;
    }
}

// -------------- Phase B (writes W fp32 + bf16 splits) -------------
__global__ void __launch_bounds__(256) phaseB_k(){
    extern __shared__ float sm[];
    float* sA = sm;
    float* sB = sm + 64*PT;
    float* sC = sm + 2*64*PT;
    int j   = blockIdx.x;
    int mat = blockIdx.y;
    float* M = g_M + (size_t)mat*FF*FF;
    float* W = g_W + (size_t)mat*FF*FF;
    uint32_t* wh = g_Whi + (size_t)mat*FF*(FF/2);
    uint32_t* wl = g_Wlo + (size_t)mat*FF*(FF/2);
    int tid = threadIdx.x, tx = tid & 15, ty = tid >> 4;
    int r0 = ty*4, c0 = tx*4;

    for (int i = j+1; i < 8; i++){
        ULL acc[4][2] = {};
        for (int k = j; k < i; k++){
            __syncthreads();
            ldt(sA, M + (size_t)(i*64)*FF + k*64, tid);
            ldt(sB, W + (size_t)(k*64)*FF + j*64, tid);
            __syncthreads();
            g64_nn(sA, sB, acc, r0, c0);
        }
        __syncthreads();
        #pragma unroll
        for (int ii = 0; ii < 4; ii++){
            float v0,v1,v2,v3;
            up2(acc[ii][0], v0, v1);
            up2(acc[ii][1], v2, v3);
            sC[(r0+ii)*PT + c0 + 0] = v0;
            sC[(r0+ii)*PT + c0 + 1] = v1;
            sC[(r0+ii)*PT + c0 + 2] = v2;
            sC[(r0+ii)*PT + c0 + 3] = v3;
        }
        ldt(sA, W + (size_t)(i*64)*FF + i*64, tid);
        __syncthreads();
        ULL acc2[4][2] = {};
        g64_nn(sA, sC, acc2, r0, c0);
        #pragma unroll
        for (int ii = 0; ii < 4; ii++){
            float v0,v1,v2,v3;
            up2(acc2[ii][0], v0, v1);
            up2(acc2[ii][1], v2, v3);
            v0 = -v0; v1 = -v1; v2 = -v2; v3 = -v3;
            float4 v = {v0,v1,v2,v3};
            size_t row = (size_t)(i*64 + r0 + ii);
            *(float4*)&W[row*FF + j*64 + c0] = v;
            uint32_t h0, l0, h1, l1;
            split2(v0, v1, h0, l0);
            split2(v2, v3, h1, l1);
            size_t o = row*(FF/2) + j*32 + (c0 >> 1);
            wh[o] = h0; wh[o+1] = h1;
            wl[o] = l0; wl[o+1] = l1;
        }
        __syncthreads();
    }
}

// ------------------------- queries split + transpose: [p][kp][q] -------------------------
__global__ void qsplit_k(const float* __restrict__ qf){
    __shared__ float sq[16][FF];
    int qb = blockIdx.x;           // 0..63 (16 queries each)
    int p  = blockIdx.y;
    int tid = threadIdx.x;
    for (int u = tid; u < 16*FF; u += 256){
        int qi = u / FF, f = u % FF;
        sq[qi][f] = qf[((size_t)p*QQ + qb*16 + qi)*FF + f];
    }
    __syncthreads();
    uint32_t* dh = g_Xhi + (size_t)p*(FF/2)*QQ;
    uint32_t* dl = g_Xlo + (size_t)p*(FF/2)*QQ;
    for (int u = tid; u < 256*16; u += 256){
        int kp = u >> 4, qi = u & 15;
        uint32_t hi, lo;
        split2(sq[qi][2*kp], sq[qi][2*kp+1], hi, lo);
        dh[(size_t)kp*QQ + qb*16 + qi] = hi;
        dl[(size_t)kp*QQ + qb*16 + qi] = lo;
    }
}

// ------------------------- y = W * mu (fp32 exact) -------------------------
__global__ void ymu_k(){
    __shared__ float smu[FF];
    int pc = blockIdx.x;
    int tid = threadIdx.x, lane = tid & 31, wid = tid >> 5;
    const float* W = g_W + (size_t)pc*FF*FF;
    for (int f = tid; f < FF; f += 256) smu[f] = g_means[(size_t)pc*FF + f];
    __syncthreads();
    for (int r = wid; r < FF; r += 8){
        float s = 0.0f;
        for (int k = lane; k <= r; k += 32)
            s += W[(size_t)r*FF + k] * smu[k];
        #pragma unroll
        for (int o = 16; o; o >>= 1) s += __shfl_xor_sync(0xFFFFFFFFu, s, o);
        if (lane == 0) g_Ymu[pc*FF + r] = s;
    }
}

// ================= quad via mma.sync bf16x3: quad = || y - W x ||^2 =================
// Grid (8 qtiles, 160 pc, 4 rb), 256 threads (8 warps: 2 m x 4 n), 2 CTAs/SM.
#define WPITCH 36
#define XPITCH 136
#define QMMA_SMEM (2*128*WPITCH*4 + 2*32*XPITCH*4 + 128*4)
__global__ void __launch_bounds__(256, 2) quadmma_k(){
    extern __shared__ uint32_t smu32[];
    uint32_t* sWhi = smu32;
    uint32_t* sWlo = sWhi + 128*WPITCH;
    uint32_t* sXhi = sWlo + 128*WPITCH;
    uint32_t* sXlo = sXhi + 32*XPITCH;
    float*    red  = (float*)(sXlo + 32*XPITCH);
    int pc = blockIdx.y;
    int p = pc / CC, c = pc % CC;
    int qbase = blockIdx.x * 128;
    int rb = blockIdx.z;
    int tid = threadIdx.x, lane = tid & 31, wid = tid >> 5;
    int g = lane >> 2, t = lane & 3;
    int warpM = wid & 1, warpN = wid >> 1;
    const uint32_t* gwh = g_Whi + (size_t)pc*FF*(FF/2);
    const uint32_t* gwl = g_Wlo + (size_t)pc*FF*(FF/2);
    const uint32_t* gxh = g_Xhi + (size_t)p*(FF/2)*QQ + qbase;
    const uint32_t* gxl = g_Xlo + (size_t)p*(FF/2)*QQ + qbase;
    const float*    ym  = g_Ymu + pc*FF;

    if (tid < 128) red[tid] = 0.0f;
    float qs[8];
    #pragma unroll
    for (int j = 0; j < 8; j++) qs[j] = 0.0f;

    float acc[4][4][4];
    #pragma unroll
    for (int mi = 0; mi < 4; mi++)
        #pragma unroll
        for (int ni = 0; ni < 4; ni++)
            #pragma unroll
            for (int r = 0; r < 4; r++) acc[mi][ni][r] = 0.0f;

    int nch = 2*rb + 2;
    for (int ch = 0; ch < nch; ch++){
        int kp0 = ch*32;
        __syncthreads();
        #pragma unroll 4
        for (int u = tid; u < 4096; u += 256){
            int r = u >> 5, kp = u & 31;
            size_t go = (size_t)(rb*128 + r)*(FF/2) + kp0 + kp;
            sWhi[r*WPITCH + kp] = gwh[go];
            sWlo[r*WPITCH + kp] = gwl[go];
        }
        #pragma unroll 4
        for (int u = tid; u < 4096; u += 256){
            int kp = u >> 7, q = u & 127;
            size_t go = (size_t)(kp0 + kp)*QQ + q;
            sXhi[kp*XPITCH + q] = gxh[go];
            sXlo[kp*XPITCH + q] = gxl[go];
        }
        __syncthreads();
        bool diag = (ch >= 2*rb);
        int kbase = (ch - 2*rb)*64;     // local k offset within 128-diag block when diag
        #pragma unroll
        for (int s = 0; s < 4; s++){
            uint32_t bh[4][2], bl[4][2];
            #pragma unroll
            for (int ni = 0; ni < 4; ni++){
                int col = warpN*32 + ni*8 + g;
                bh[ni][0] = sXhi[(8*s + t)*XPITCH + col];
                bh[ni][1] = sXhi[(8*s + t + 4)*XPITCH + col];
                bl[ni][0] = sXlo[(8*s + t)*XPITCH + col];
                bl[ni][1] = sXlo[(8*s + t + 4)*XPITCH + col];
            }
            #pragma unroll
            for (int mi = 0; mi < 4; mi++){
                if (diag && (warpM*64 + mi*16 + 16 <= kbase + 16*s)) continue;
                int row = warpM*64 + mi*16 + g;
                uint32_t ah0 = sWhi[row*WPITCH + 8*s + t];
                uint32_t ah1 = sWhi[(row+8)*WPITCH + 8*s + t];
                uint32_t ah2 = sWhi[row*WPITCH + 8*s + t + 4];
                uint32_t ah3 = sWhi[(row+8)*WPITCH + 8*s + t + 4];
                uint32_t al0 = sWlo[row*WPITCH + 8*s + t];
                uint32_t al1 = sWlo[(row+8)*WPITCH + 8*s + t];
                uint32_t al2 = sWlo[row*WPITCH + 8*s + t + 4];
                uint32_t al3 = sWlo[(row+8)*WPITCH + 8*s + t + 4];
                #pragma unroll
                for (int ni = 0; ni < 4; ni++){
                    MMA_BF16(acc[mi][ni], ah0,ah1,ah2,ah3, bh[ni][0],bh[ni][1]);
                    MMA_BF16(acc[mi][ni], ah0,ah1,ah2,ah3, bl[ni][0],bl[ni][1]);
                    MMA_BF16(acc[mi][ni], al0,al1,al2,al3, bh[ni][0],bh[ni][1]);
                }
            }
        }
    }
    // epilogue: qs += (y - z)^2 over this CTA's 128 rows
    #pragma unroll
    for (int mi = 0; mi < 4; mi++){
        int r1 = rb*128 + warpM*64 + mi*16 + g;
        float y1 = ym[r1], y2 = ym[r1 + 8];
        #pragma unroll
        for (int ni = 0; ni < 4; ni++){
            float d0 = y1 - acc[mi][ni][0];
            float d1 = y1 - acc[mi][ni][1];
            float d2 = y2 - acc[mi][ni][2];
            float d3 = y2 - acc[mi][ni][3];
            qs[2*ni]   += d0*d0 + d2*d2;
            qs[2*ni+1] += d1*d1 + d3*d3;
        }
    }

    #pragma unroll
    for (int j = 0; j < 8; j++)
        #pragma unroll
        for (int o = 4; o < 32; o <<= 1)
            qs[j] += __shfl_xor_sync(0xFFFFFFFFu, qs[j], o);
    if (lane < 4){
        #pragma unroll
        for (int j = 0; j < 8; j++){
            int ni = j >> 1, b = j & 1;
            int q = warpN*32 + ni*8 + 2*lane + b;
            atomicAdd(&red[q], qs[j]);
        }
    }
    __syncthreads();
    if (tid < 128)
        atomicAdd(&g_quad[((size_t)p*QQ + qbase + tid)*CC + c], red[tid]);
}

// ------------------------- final outputs -------------------------
__global__ void logits_k(float* out){
    int q = blockIdx.x;
    int c = threadIdx.x;
    if (c < CC){
        float s = 0.0f;
        #pragma unroll
        for (int p = 0; p < PP; p++) s += g_quad[((size_t)p*QQ + q)*CC + c];
        out[q*CC + c] = -s * (1.0f/PP);
    }
}
__global__ void copymeans_k(float* out){
    for (int i = blockIdx.x*blockDim.x + threadIdx.x; i < NM*FF; i += gridDim.x*blockDim.x)
        out[QQ*CC + i] = g_means[i];
}

// ------------------------- launch -------------------------
extern "C" void kernel_launch(void* const* d_in, const int* in_sizes, int n_in,
                              void* d_out, int out_size) {
    const float* sf  = (const float*)d_in[0];
    const int*   lab = (const int*)d_in[1];
    const float* qf  = (const float*)d_in[2];
    float* out = (float*)d_out;

    const int CHOL_SMEM = 3*64*PT*(int)sizeof(float);
    const int TR_SMEM   = 2*64*PT*(int)sizeof(float);
    cudaFuncSetAttribute(diagpanel_k, cudaFuncAttributeMaxDynamicSharedMemorySize, CHOL_SMEM);
    cudaFuncSetAttribute(phaseB_k,    cudaFuncAttributeMaxDynamicSharedMemorySize, CHOL_SMEM);
    cudaFuncSetAttribute(quadmma_k,   cudaFuncAttributeMaxDynamicSharedMemorySize, QMMA_SMEM);

    setup_k<<<1, 32>>>(lab);
    means_k<<<NM, 256>>>(sf);
    tm_k<<<PP, 256>>>(sf);
    qsplit_k<<<dim3(64, PP), 256>>>(qf);
    taskcov_k<<<dim3(36, PP), 256>>>(sf);
    buildM_k<<<dim3(36, NM), 256>>>(sf);
    zeroWu_k<<<dim3(4, NM), 256>>>();
    zeroquad_k<<<160, 256>>>();
    for (int j = 0; j < 8; j++){
        diagpanel_k<<<NM, 256, CHOL_SMEM>>>(j);
        int nt = (7-j)*(8-j)/2;
        if (nt > 0)
            trailing_k<<<dim3(nt, NM), 256, TR_SMEM>>>(j);
    }
    phaseB_k<<<dim3(7, NM), 256, CHOL_SMEM>>>();
    ymu_k<<<NM, 256>>>();
    quadmma_k<<<dim3(8, NM, 4), 256, QMMA_SMEM>>>();
    logits_k<<<QQ, 32>>>(out);
    if (out_size >= QQ*CC + NM*FF)
        copymeans_k<<<160, 512>>>(out);
}

// round 8
// speedup vs baseline: 1.5673x; 1.0473x over previous
#include <cuda_runtime.h>
#include <cuda_bf16.h>
#include <math.h>
#include <stdint.h>

#define PP 8
#define TT 200
#define FF 512
#define CC 20
#define QQ 1024
#define NM (PP*CC)
typedef unsigned long long ULL;

// ------------------------- device scratch -------------------------
__device__ float g_means[NM*FF];
__device__ float g_tm[PP*FF];
__device__ float g_task[(size_t)PP*FF*FF];
__device__ float g_M[(size_t)NM*FF*FF];            // cov_reg -> L (in place)
__device__ float g_W[(size_t)NM*FF*FF];            // W = L^{-1}
__device__ float g_quad[(size_t)PP*QQ*CC];
__device__ float g_Ymu[NM*FF];                     // y = W * mu (fp32 exact)
__device__ uint32_t g_Whi[(size_t)NM*FF*(FF/2)];   // bf16 pairs along k
__device__ uint32_t g_Wlo[(size_t)NM*FF*(FF/2)];
__device__ uint32_t g_Xhi[(size_t)PP*(FF/2)*QQ];   // [p][kp][q]
__device__ uint32_t g_Xlo[(size_t)PP*(FF/2)*QQ];
__device__ int   g_members[CC*TT];
__device__ int   g_cnt[CC];
__device__ float g_icnts[CC], g_sclS[CC], g_sclT[CC];

// ------------------------- f32x2 helpers -------------------------
__device__ __forceinline__ ULL pk2(float lo, float hi){
    ULL r; asm("mov.b64 %0, {%1,%2};" : "=l"(r) : "f"(lo), "f"(hi)); return r;
}
__device__ __forceinline__ void up2(ULL v, float &a, float &b){
    asm("mov.b64 {%0,%1}, %2;" : "=f"(a), "=f"(b) : "l"(v));
}
__device__ __forceinline__ void fma2(ULL &d, ULL a, ULL b){
    asm("fma.rn.f32x2 %0, %1, %2, %0;" : "+l"(d) : "l"(a), "l"(b));
}

// ------------------------- bf16 split helper -------------------------
__device__ __forceinline__ void split2(float x0, float x1, uint32_t &hi, uint32_t &lo){
    __nv_bfloat16 h0 = __float2bfloat16(x0);
    __nv_bfloat16 h1 = __float2bfloat16(x1);
    float r0 = x0 - __bfloat162float(h0);
    float r1 = x1 - __bfloat162float(h1);
    __nv_bfloat16 l0 = __float2bfloat16(r0);
    __nv_bfloat16 l1 = __float2bfloat16(r1);
    hi = (uint32_t)__bfloat16_as_ushort(h0) | ((uint32_t)__bfloat16_as_ushort(h1) << 16);
    lo = (uint32_t)__bfloat16_as_ushort(l0) | ((uint32_t)__bfloat16_as_ushort(l1) << 16);
}

#define MMA_BF16(c, a0,a1,a2,a3, b0,b1) \
    asm volatile("mma.sync.aligned.m16n8k16.row.col.f32.bf16.bf16.f32 " \
        "{%0,%1,%2,%3},{%4,%5,%6,%7},{%8,%9},{%0,%1,%2,%3};" \
        : "+f"(c[0]),"+f"(c[1]),"+f"(c[2]),"+f"(c[3]) \
        : "r"(a0),"r"(a1),"r"(a2),"r"(a3),"r"(b0),"r"(b1))

__device__ __forceinline__ void ldm4(uint32_t &r0, uint32_t &r1, uint32_t &r2, uint32_t &r3,
                                     uint32_t saddr){
    asm volatile("ldmatrix.sync.aligned.m8n8.x4.shared.b16 {%0,%1,%2,%3}, [%4];"
        : "=r"(r0), "=r"(r1), "=r"(r2), "=r"(r3) : "r"(saddr));
}
__device__ __forceinline__ uint32_t smem_u32(const void* p){
    uint32_t a;
    asm("{ .reg .u64 t; cvta.to.shared.u64 t, %1; cvt.u32.u64 %0, t; }" : "=r"(a) : "l"(p));
    return a;
}

// ------------------------- setup -------------------------
__global__ void setup_k(const int* __restrict__ lab_raw){
    if (threadIdx.x == 0 && blockIdx.x == 0){
        bool odd_all_zero = true;
        for (int t = 1; t < 200; t += 2) if (lab_raw[t] != 0) odd_all_zero = false;
        bool even_has_big = false;
        for (int t = 0; t < 200; t += 2) if (lab_raw[t] > 0) even_has_big = true;
        bool is64 = odd_all_zero && even_has_big;

        int cnt[CC];
        #pragma unroll
        for (int c = 0; c < CC; c++) cnt[c] = 0;
        for (int t = 0; t < TT; t++){
            int cc = is64 ? lab_raw[2*t] : lab_raw[t];
            if (cc < 0) cc = 0; if (cc >= CC) cc = CC-1;
            g_members[cc*TT + cnt[cc]] = t;
            cnt[cc]++;
        }
        for (int c = 0; c < CC; c++){
            g_cnt[c] = cnt[c];
            float cs  = fmaxf((float)cnt[c], 1.0f);
            g_icnts[c] = 1.0f / cs;
            float lam = cs / (cs + 1.0f);
            g_sclS[c] = lam / fmaxf((float)cnt[c] - 1.0f, 1.0f);
            g_sclT[c] = 1.0f - lam;
        }
    }
}

// ------------------------- class means -------------------------
__global__ void means_k(const float* __restrict__ sf){
    int pc = blockIdx.x;
    int p = pc / CC, c = pc % CC;
    int n = g_cnt[c];
    float ic = g_icnts[c];
    for (int f = threadIdx.x; f < FF; f += blockDim.x){
        float s = 0.0f;
        for (int m = 0; m < n; m++){
            int t = g_members[c*TT + m];
            s += sf[((size_t)p*TT + t)*FF + f];
        }
        g_means[(size_t)pc*FF + f] = s * ic;
    }
}

// ------------------------- task mean -------------------------
__global__ void tm_k(const float* __restrict__ sf){
    int p = blockIdx.x;
    for (int f = threadIdx.x; f < FF; f += blockDim.x){
        float s = 0.0f;
        for (int t = 0; t < TT; t++) s += sf[((size_t)p*TT + t)*FF + f];
        g_tm[p*FF + f] = s * (1.0f/TT);
    }
}

// ------------------------- task covariance -------------------------
__global__ void taskcov_k(const float* __restrict__ sf){
    int tile = blockIdx.x;          // 0..35 (tg<=tf)
    int p    = blockIdx.y;
    int tf = 0, rem = tile;
    while (rem >= tf+1){ rem -= tf+1; tf++; }
    int tg = rem;
    __shared__ float af[8][68], ag[8][68];
    int tid = threadIdx.x, tx = tid & 15, ty = tid >> 4;
    int r0 = ty*4, c0 = tx*4;
    float acc[4][4] = {};
    const float* tmv = g_tm + p*FF;
    for (int t0 = 0; t0 < TT; t0 += 8){
        __syncthreads();
        #pragma unroll
        for (int ii = 0; ii < 2; ii++){
            int idx = ii*256 + tid;
            int s = idx >> 6, f = idx & 63;
            const float* row = sf + ((size_t)p*TT + t0 + s)*FF;
            af[s][f] = row[tf*64 + f] - tmv[tf*64 + f];
            ag[s][f] = row[tg*64 + f] - tmv[tg*64 + f];
        }
        __syncthreads();
        #pragma unroll
        for (int s = 0; s < 8; s++){
            float a[4], b[4];
            #pragma unroll
            for (int i = 0; i < 4; i++) a[i] = af[s][r0+i];
            #pragma unroll
            for (int j = 0; j < 4; j++) b[j] = ag[s][c0+j];
            #pragma unroll
            for (int i = 0; i < 4; i++)
                #pragma unroll
                for (int j = 0; j < 4; j++) acc[i][j] += a[i]*b[j];
        }
    }
    const float inv = 1.0f/(TT-1);
    float* dst = g_task + (size_t)p*FF*FF;
    #pragma unroll
    for (int i = 0; i < 4; i++)
        #pragma unroll
        for (int j = 0; j < 4; j++){
            int fr = tf*64 + r0 + i, gc = tg*64 + c0 + j;
            float v = acc[i][j]*inv;
            dst[(size_t)fr*FF + gc] = v;
            dst[(size_t)gc*FF + fr] = v;
        }
}

// ------------------------- cov_reg -------------------------
__global__ void buildM_k(const float* __restrict__ sf){
    int tile = blockIdx.x;          // 0..35
    int pc   = blockIdx.y;
    int p = pc / CC, c = pc % CC;
    int tf = 0, rem = tile;
    while (rem >= tf+1){ rem -= tf+1; tf++; }
    int tg = rem;
    __shared__ float af[4][68], ag[4][68];
    int tid = threadIdx.x, tx = tid & 15, ty = tid >> 4;
    int r0 = ty*4, c0 = tx*4;
    float acc[4][4] = {};
    int n = g_cnt[c];
    const float* mu = g_means + (size_t)pc*FF;
    for (int m0 = 0; m0 < n; m0 += 4){
        __syncthreads();
        {
            int s = tid >> 6, f = tid & 63;
            int m = m0 + s;
            float va = 0.0f, vg = 0.0f;
            if (m < n){
                int t = g_members[c*TT + m];
                const float* row = sf + ((size_t)p*TT + t)*FF;
                va = row[tf*64 + f] - mu[tf*64 + f];
                vg = row[tg*64 + f] - mu[tg*64 + f];
            }
            af[s][f] = va; ag[s][f] = vg;
        }
        __syncthreads();
        #pragma unroll
        for (int s = 0; s < 4; s++){
            float a[4], b[4];
            #pragma unroll
            for (int i = 0; i < 4; i++) a[i] = af[s][r0+i];
            #pragma unroll
            for (int j = 0; j < 4; j++) b[j] = ag[s][c0+j];
            #pragma unroll
            for (int i = 0; i < 4; i++)
                #pragma unroll
                for (int j = 0; j < 4; j++) acc[i][j] += a[i]*b[j];
        }
    }
    float ss = g_sclS[c], st = g_sclT[c];
    float* dst = g_M + (size_t)pc*FF*FF;
    const float* tk = g_task + (size_t)p*FF*FF;
    #pragma unroll
    for (int i = 0; i < 4; i++)
        #pragma unroll
        for (int j = 0; j < 4; j++){
            int fr = tf*64 + r0 + i, gc = tg*64 + c0 + j;
            float v = ss*acc[i][j] + st*tk[(size_t)fr*FF + gc] + ((fr == gc) ? 1.0f : 0.0f);
            dst[(size_t)fr*FF + gc] = v;
            dst[(size_t)gc*FF + fr] = v;
        }
}

// -------- zero split arrays in the upper-right 64x64 of each 128-diag block --------
__global__ void zeroWu_k(){
    int rb  = blockIdx.x;
    int mat = blockIdx.y;
    uint32_t* wh = g_Whi + (size_t)mat*FF*(FF/2);
    uint32_t* wl = g_Wlo + (size_t)mat*FF*(FF/2);
    for (int e = threadIdx.x; e < 64*32; e += 256){
        int r = e >> 5, cp = e & 31;
        size_t o = (size_t)(rb*128 + r)*(FF/2) + rb*64 + 32 + cp;
        wh[o] = 0u; wl[o] = 0u;
    }
}

// -------- zero g_quad --------
__global__ void zeroquad_k(){
    size_t n = (size_t)PP*QQ*CC;
    for (size_t i = (size_t)blockIdx.x*blockDim.x + threadIdx.x; i < n;
         i += (size_t)gridDim.x*blockDim.x)
        g_quad[i] = 0.0f;
}

// ------------------------- 64x64 helpers (pitch 65) -------------------------
#define PT 65
__device__ __forceinline__ void ldt(float* dst, const float* g, int tid){
    #pragma unroll 4
    for (int e = tid; e < 4096; e += 256){
        int r = e >> 6, c = e & 63;
        dst[r*PT + c] = g[(size_t)r*FF + c];
    }
}
__device__ __forceinline__ void g64_nt(const float* A, const float* B,
                                       ULL acc[4][2], int r0, int c0){
    #pragma unroll 4
    for (int k = 0; k < 64; k++){
        ULL b01 = pk2(B[(c0+0)*PT+k], B[(c0+1)*PT+k]);
        ULL b23 = pk2(B[(c0+2)*PT+k], B[(c0+3)*PT+k]);
        #pragma unroll
        for (int i = 0; i < 4; i++){
            float a = A[(r0+i)*PT+k];
            ULL aa = pk2(a, a);
            fma2(acc[i][0], aa, b01);
            fma2(acc[i][1], aa, b23);
        }
    }
}
__device__ __forceinline__ void g64_nn(const float* A, const float* B,
                                       ULL acc[4][2], int r0, int c0){
    #pragma unroll 4
    for (int k = 0; k < 64; k++){
        ULL b01 = pk2(B[k*PT+c0+0], B[k*PT+c0+1]);
        ULL b23 = pk2(B[k*PT+c0+2], B[k*PT+c0+3]);
        #pragma unroll
        for (int i = 0; i < 4; i++){
            float a = A[(r0+i)*PT+k];
            ULL aa = pk2(a, a);
            fma2(acc[i][0], aa, b01);
            fma2(acc[i][1], aa, b23);
        }
    }
}

// -------------- Phase A step j: diag factor + tri-inverse + panel --------
__global__ void __launch_bounds__(256) diagpanel_k(int j){
    extern __shared__ float sm[];
    float* sA = sm;
    float* sB = sm + 64*PT;
    float* sC = sm + 2*64*PT;
    int mat = blockIdx.x;
    float* M = g_M + (size_t)mat*FF*FF;
    float* W = g_W + (size_t)mat*FF*FF;
    int tid = threadIdx.x, tx = tid & 15, ty = tid >> 4;
    int r0 = ty*4, c0 = tx*4;

    ldt(sA, M + (size_t)(j*64)*FF + j*64, tid);
    __syncthreads();
    for (int k = 0; k < 64; k++){
        float pinv = 1.0f / sA[k*PT+k];
        #pragma unroll 4
        for (int e = tid; e < 4096; e += 256){
            int r = e >> 6, cc = e & 63;
            if (r > k && cc > k && cc <= r)
                sA[r*PT+cc] -= sA[r*PT+k]*sA[cc*PT+k]*pinv;
        }
        __syncthreads();
    }
    if (tid < 64) sC[tid] = rsqrtf(sA[tid*PT+tid]);
    __syncthreads();
    #pragma unroll 4
    for (int e = tid; e < 4096; e += 256){
        int r = e >> 6, cc = e & 63;
        if (cc <= r) sA[r*PT+cc] *= sC[cc];
    }
    __syncthreads();

    #pragma unroll 4
    for (int e = tid; e < 4096; e += 256) sB[(e>>6)*PT + (e&63)] = 0.0f;
    __syncthreads();
    {
        int c = tid >> 2, s = tid & 3;
        unsigned gmask = 0xFu << ((tid & 31) & ~3);
        float dv = 1.0f / sA[c*PT+c];
        if (s == 0) sB[c*PT+c] = dv;
        __syncwarp(gmask);
        for (int r = c+1; r < 64; r++){
            float part = 0.0f;
            for (int k2 = c + s; k2 < r; k2 += 4)
                part += sA[r*PT+k2] * sB[k2*PT+c];
            part += __shfl_xor_sync(gmask, part, 1);
            part += __shfl_xor_sync(gmask, part, 2);
            if (s == 0) sB[r*PT+c] = -part / sA[r*PT+r];
            __syncwarp(gmask);
        }
    }
    __syncthreads();
    #pragma unroll 4
    for (int e = tid; e < 4096; e += 256){
        int r = e >> 6, cc = e & 63;
        W[(size_t)(j*64 + r)*FF + j*64 + cc] = sB[r*PT+cc];
    }
    {
        uint32_t* wh = g_Whi + (size_t)mat*FF*(FF/2);
        uint32_t* wl = g_Wlo + (size_t)mat*FF*(FF/2);
        for (int e = tid; e < 2048; e += 256){
            int r = e >> 5, cp = e & 31;
            uint32_t hi, lo;
            split2(sB[r*PT + 2*cp], sB[r*PT + 2*cp + 1], hi, lo);
            size_t o = (size_t)(j*64 + r)*(FF/2) + j*32 + cp;
            wh[o] = hi; wl[o] = lo;
        }
    }
    for (int i = j+1; i < 8; i++){
        __syncthreads();
        ldt(sC, M + (size_t)(i*64)*FF + j*64, tid);
        __syncthreads();
        ULL acc[4][2] = {};
        g64_nt(sC, sB, acc, r0, c0);
        #pragma unroll
        for (int ii = 0; ii < 4; ii++){
            float v0,v1,v2,v3;
            up2(acc[ii][0], v0, v1);
            up2(acc[ii][1], v2, v3);
            float4 v = {v0,v1,v2,v3};
            *(float4*)&M[(size_t)(i*64 + r0 + ii)*FF + j*64 + c0] = v;
        }
    }
}

// -------------- Phase A trailing -------------
__global__ void __launch_bounds__(256) trailing_k(int j){
    extern __shared__ float sm[];
    float* sA = sm;
    float* sB = sm + 64*PT;
    int mat = blockIdx.y;
    int t = blockIdx.x;
    int i = j+1, cnt = 1;
    while (t >= cnt){ t -= cnt; i++; cnt = i - j; }
    int kk = j+1 + t;
    float* M = g_M + (size_t)mat*FF*FF;
    int tid = threadIdx.x, tx = tid & 15, ty = tid >> 4;
    int r0 = ty*4, c0 = tx*4;
    ldt(sA, M + (size_t)(i*64)*FF + j*64, tid);
    ldt(sB, M + (size_t)(kk*64)*FF + j*64, tid);
    __syncthreads();
    ULL acc[4][2] = {};
    g64_nt(sA, sB, acc, r0, c0);
    #pragma unroll
    for (int ii = 0; ii < 4; ii++){
        float v0,v1,v2,v3;
        up2(acc[ii][0], v0, v1);
        up2(acc[ii][1], v2, v3);
        float4* dst = (float4*)&M[(size_t)(i*64 + r0 + ii)*FF + kk*64 + c0];
        float4 v = *dst;
        v.x -= v0; v.y -= v1; v.z -= v2; v.w -= v3;
        *dst = v;
    }
}

// -------------- Phase B (writes W fp32 + bf16 splits) -------------
__global__ void __launch_bounds__(256) phaseB_k(){
    extern __shared__ float sm[];
    float* sA = sm;
    float* sB = sm + 64*PT;
    float* sC = sm + 2*64*PT;
    int j   = blockIdx.x;
    int mat = blockIdx.y;
    float* M = g_M + (size_t)mat*FF*FF;
    float* W = g_W + (size_t)mat*FF*FF;
    uint32_t* wh = g_Whi + (size_t)mat*FF*(FF/2);
    uint32_t* wl = g_Wlo + (size_t)mat*FF*(FF/2);
    int tid = threadIdx.x, tx = tid & 15, ty = tid >> 4;
    int r0 = ty*4, c0 = tx*4;

    for (int i = j+1; i < 8; i++){
        ULL acc[4][2] = {};
        for (int k = j; k < i; k++){
            __syncthreads();
            ldt(sA, M + (size_t)(i*64)*FF + k*64, tid);
            ldt(sB, W + (size_t)(k*64)*FF + j*64, tid);
            __syncthreads();
            g64_nn(sA, sB, acc, r0, c0);
        }
        __syncthreads();
        #pragma unroll
        for (int ii = 0; ii < 4; ii++){
            float v0,v1,v2,v3;
            up2(acc[ii][0], v0, v1);
            up2(acc[ii][1], v2, v3);
            sC[(r0+ii)*PT + c0 + 0] = v0;
            sC[(r0+ii)*PT + c0 + 1] = v1;
            sC[(r0+ii)*PT + c0 + 2] = v2;
            sC[(r0+ii)*PT + c0 + 3] = v3;
        }
        ldt(sA, W + (size_t)(i*64)*FF + i*64, tid);
        __syncthreads();
        ULL acc2[4][2] = {};
        g64_nn(sA, sC, acc2, r0, c0);
        #pragma unroll
        for (int ii = 0; ii < 4; ii++){
            float v0,v1,v2,v3;
            up2(acc2[ii][0], v0, v1);
            up2(acc2[ii][1], v2, v3);
            v0 = -v0; v1 = -v1; v2 = -v2; v3 = -v3;
            float4 v = {v0,v1,v2,v3};
            size_t row = (size_t)(i*64 + r0 + ii);
            *(float4*)&W[row*FF + j*64 + c0] = v;
            uint32_t h0, l0, h1, l1;
            split2(v0, v1, h0, l0);
            split2(v2, v3, h1, l1);
            size_t o = row*(FF/2) + j*32 + (c0 >> 1);
            wh[o] = h0; wh[o+1] = h1;
            wl[o] = l0; wl[o+1] = l1;
        }
        __syncthreads();
    }
}

// ------------------------- queries split + transpose: [p][kp][q] -------------------------
__global__ void qsplit_k(const float* __restrict__ qf){
    __shared__ float sq[16][FF];
    int qb = blockIdx.x;           // 0..63 (16 queries each)
    int p  = blockIdx.y;
    int tid = threadIdx.x;
    for (int u = tid; u < 16*FF; u += 256){
        int qi = u / FF, f = u % FF;
        sq[qi][f] = qf[((size_t)p*QQ + qb*16 + qi)*FF + f];
    }
    __syncthreads();
    uint32_t* dh = g_Xhi + (size_t)p*(FF/2)*QQ;
    uint32_t* dl = g_Xlo + (size_t)p*(FF/2)*QQ;
    for (int u = tid; u < 256*16; u += 256){
        int kp = u >> 4, qi = u & 15;
        uint32_t hi, lo;
        split2(sq[qi][2*kp], sq[qi][2*kp+1], hi, lo);
        dh[(size_t)kp*QQ + qb*16 + qi] = hi;
        dl[(size_t)kp*QQ + qb*16 + qi] = lo;
    }
}

// ------------------------- y = W * mu (fp32 exact) -------------------------
__global__ void ymu_k(){
    __shared__ float smu[FF];
    int pc = blockIdx.x;
    int tid = threadIdx.x, lane = tid & 31, wid = tid >> 5;
    const float* W = g_W + (size_t)pc*FF*FF;
    for (int f = tid; f < FF; f += 256) smu[f] = g_means[(size_t)pc*FF + f];
    __syncthreads();
    for (int r = wid; r < FF; r += 8){
        float s = 0.0f;
        for (int k = lane; k <= r; k += 32)
            s += W[(size_t)r*FF + k] * smu[k];
        #pragma unroll
        for (int o = 16; o; o >>= 1) s += __shfl_xor_sync(0xFFFFFFFFu, s, o);
        if (lane == 0) g_Ymu[pc*FF + r] = s;
    }
}

// ================= quad via mma.sync bf16x3: quad = || y - W x ||^2 =================
// Grid (8 qtiles, 160 pc, 4 rb), 256 threads (8 warps: 2 m x 4 n), 2 CTAs/SM.
#define WPITCH 36
#define XPITCH 136
#define QMMA_SMEM (2*128*WPITCH*4 + 2*32*XPITCH*4 + 128*4)
__global__ void __launch_bounds__(256, 2) quadmma_k(){
    extern __shared__ uint32_t smu32[];
    uint32_t* sWhi = smu32;
    uint32_t* sWlo = sWhi + 128*WPITCH;
    uint32_t* sXhi = sWlo + 128*WPITCH;
    uint32_t* sXlo = sXhi + 32*XPITCH;
    float*    red  = (float*)(sXlo + 32*XPITCH);
    int pc = blockIdx.y;
    int p = pc / CC, c = pc % CC;
    int qbase = blockIdx.x * 128;
    int rb = blockIdx.z;
    int tid = threadIdx.x, lane = tid & 31, wid = tid >> 5;
    int g = lane >> 2, t = lane & 3;
    int warpM = wid & 1, warpN = wid >> 1;
    // ldmatrix lane address components
    int lm_row = (lane & 7) + ((lane >> 3) & 1)*8;
    int lm_col = (lane >> 4)*4;
    uint32_t sWhi_b = smem_u32(sWhi);
    uint32_t sWlo_b = smem_u32(sWlo);
    const uint4* gwh4 = (const uint4*)(g_Whi + (size_t)pc*FF*(FF/2));
    const uint4* gwl4 = (const uint4*)(g_Wlo + (size_t)pc*FF*(FF/2));
    const uint4* gxh4 = (const uint4*)(g_Xhi + (size_t)p*(FF/2)*QQ + qbase);
    const uint4* gxl4 = (const uint4*)(g_Xlo + (size_t)p*(FF/2)*QQ + qbase);
    const float* ym = g_Ymu + pc*FF;

    if (tid < 128) red[tid] = 0.0f;
    float qs[8];
    #pragma unroll
    for (int j = 0; j < 8; j++) qs[j] = 0.0f;

    float acc[4][4][4];
    #pragma unroll
    for (int mi = 0; mi < 4; mi++)
        #pragma unroll
        for (int ni = 0; ni < 4; ni++)
            #pragma unroll
            for (int r = 0; r < 4; r++) acc[mi][ni][r] = 0.0f;

    int nch = 2*rb + 2;
    for (int ch = 0; ch < nch; ch++){
        int kp0 = ch*32;
        __syncthreads();
        // stage W tiles (uint4): row r, 8 uint4 across 32 kp
        #pragma unroll
        for (int u = tid; u < 1024; u += 256){
            int r = u >> 3, c4 = u & 7;
            size_t go = (size_t)(rb*128 + r)*(FF/8) + (kp0 >> 2) + c4;
            *(uint4*)&sWhi[r*WPITCH + c4*4] = gwh4[go];
            *(uint4*)&sWlo[r*WPITCH + c4*4] = gwl4[go];
        }
        // stage X tiles (uint4): row kp, 32 uint4 across 128 q
        #pragma unroll
        for (int u = tid; u < 1024; u += 256){
            int kp = u >> 5, q4 = u & 31;
            size_t go = (size_t)(kp0 + kp)*(QQ/4) + q4;
            *(uint4*)&sXhi[kp*XPITCH + q4*4] = gxh4[go];
            *(uint4*)&sXlo[kp*XPITCH + q4*4] = gxl4[go];
        }
        __syncthreads();
        bool diag = (ch >= 2*rb);
        int kbase = (ch - 2*rb)*64;
        #pragma unroll
        for (int s = 0; s < 4; s++){
            uint32_t bh[4][2], bl[4][2];
            #pragma unroll
            for (int ni = 0; ni < 4; ni++){
                int col = warpN*32 + ni*8 + g;
                bh[ni][0] = sXhi[(8*s + t)*XPITCH + col];
                bh[ni][1] = sXhi[(8*s + t + 4)*XPITCH + col];
                bl[ni][0] = sXlo[(8*s + t)*XPITCH + col];
                bl[ni][1] = sXlo[(8*s + t + 4)*XPITCH + col];
            }
            #pragma unroll
            for (int mi = 0; mi < 4; mi++){
                if (diag && (warpM*64 + mi*16 + 16 <= kbase + 16*s)) continue;
                uint32_t off = (uint32_t)(((warpM*64 + mi*16 + lm_row)*WPITCH + 8*s + lm_col)*4);
                uint32_t ah0,ah1,ah2,ah3, al0,al1,al2,al3;
                ldm4(ah0,ah1,ah2,ah3, sWhi_b + off);
                ldm4(al0,al1,al2,al3, sWlo_b + off);
                #pragma unroll
                for (int ni = 0; ni < 4; ni++){
                    MMA_BF16(acc[mi][ni], ah0,ah1,ah2,ah3, bh[ni][0],bh[ni][1]);
                    MMA_BF16(acc[mi][ni], ah0,ah1,ah2,ah3, bl[ni][0],bl[ni][1]);
                    MMA_BF16(acc[mi][ni], al0,al1,al2,al3, bh[ni][0],bh[ni][1]);
                }
            }
        }
    }
    // epilogue: qs += (y - z)^2 over this CTA's 128 rows
    #pragma unroll
    for (int mi = 0; mi < 4; mi++){
        int r1 = rb*128 + warpM*64 + mi*16 + g;
        float y1 = ym[r1], y2 = ym[r1 + 8];
        #pragma unroll
        for (int ni = 0; ni < 4; ni++){
            float d0 = y1 - acc[mi][ni][0];
            float d1 = y1 - acc[mi][ni][1];
            float d2 = y2 - acc[mi][ni][2];
            float d3 = y2 - acc[mi][ni][3];
            qs[2*ni]   += d0*d0 + d2*d2;
            qs[2*ni+1] += d1*d1 + d3*d3;
        }
    }

    #pragma unroll
    for (int j = 0; j < 8; j++)
        #pragma unroll
        for (int o = 4; o < 32; o <<= 1)
            qs[j] += __shfl_xor_sync(0xFFFFFFFFu, qs[j], o);
    if (lane < 4){
        #pragma unroll
        for (int j = 0; j < 8; j++){
            int ni = j >> 1, b = j & 1;
            int q = warpN*32 + ni*8 + 2*lane + b;
            atomicAdd(&red[q], qs[j]);
        }
    }
    __syncthreads();
    if (tid < 128)
        atomicAdd(&g_quad[((size_t)p*QQ + qbase + tid)*CC + c], red[tid]);
}

// ------------------------- final outputs -------------------------
__global__ void logits_k(float* out){
    int q = blockIdx.x;
    int c = threadIdx.x;
    if (c < CC){
        float s = 0.0f;
        #pragma unroll
        for (int p = 0; p < PP; p++) s += g_quad[((size_t)p*QQ + q)*CC + c];
        out[q*CC + c] = -s * (1.0f/PP);
    }
}
__global__ void copymeans_k(float* out){
    for (int i = blockIdx.x*blockDim.x + threadIdx.x; i < NM*FF; i += gridDim.x*blockDim.x)
        out[QQ*CC + i] = g_means[i];
}

// ------------------------- launch -------------------------
extern "C" void kernel_launch(void* const* d_in, const int* in_sizes, int n_in,
                              void* d_out, int out_size) {
    const float* sf  = (const float*)d_in[0];
    const int*   lab = (const int*)d_in[1];
    const float* qf  = (const float*)d_in[2];
    float* out = (float*)d_out;

    const int CHOL_SMEM = 3*64*PT*(int)sizeof(float);
    const int TR_SMEM   = 2*64*PT*(int)sizeof(float);
    cudaFuncSetAttribute(diagpanel_k, cudaFuncAttributeMaxDynamicSharedMemorySize, CHOL_SMEM);
    cudaFuncSetAttribute(phaseB_k,    cudaFuncAttributeMaxDynamicSharedMemorySize, CHOL_SMEM);
    cudaFuncSetAttribute(quadmma_k,   cudaFuncAttributeMaxDynamicSharedMemorySize, QMMA_SMEM);

    setup_k<<<1, 32>>>(lab);
    means_k<<<NM, 256>>>(sf);
    tm_k<<<PP, 256>>>(sf);
    qsplit_k<<<dim3(64, PP), 256>>>(qf);
    taskcov_k<<<dim3(36, PP), 256>>>(sf);
    buildM_k<<<dim3(36, NM), 256>>>(sf);
    zeroWu_k<<<dim3(4, NM), 256>>>();
    zeroquad_k<<<160, 256>>>();
    for (int j = 0; j < 8; j++){
        diagpanel_k<<<NM, 256, CHOL_SMEM>>>(j);
        int nt = (7-j)*(8-j)/2;
        if (nt > 0)
            trailing_k<<<dim3(nt, NM), 256, TR_SMEM>>>(j);
    }
    phaseB_k<<<dim3(7, NM), 256, CHOL_SMEM>>>();
    ymu_k<<<NM, 256>>>();
    quadmma_k<<<dim3(8, NM, 4), 256, QMMA_SMEM>>>();
    logits_k<<<QQ, 32>>>(out);
    if (out_size >= QQ*CC + NM*FF)
        copymeans_k<<<160, 512>>>(out);
}

// round 9
// speedup vs baseline: 1.8823x; 1.2010x over previous
#include <cuda_runtime.h>
#include <cuda_bf16.h>
#include <math.h>
#include <stdint.h>

#define PP 8
#define TT 200
#define FF 512
#define CC 20
#define QQ 1024
#define NM (PP*CC)
typedef unsigned long long ULL;

// ------------------------- device scratch -------------------------
__device__ float g_means[NM*FF];
__device__ float g_tm[PP*FF];
__device__ float g_task[(size_t)PP*FF*FF];
__device__ float g_M[(size_t)NM*FF*FF];            // cov_reg -> L (in place)
__device__ float g_W[(size_t)NM*FF*FF];            // W = L^{-1} (fp32)
__device__ float g_quad[(size_t)PP*QQ*CC];
__device__ float g_Ymu[NM*FF];                     // y = W * mu (fp32 exact)
__device__ uint32_t g_Whi[(size_t)NM*FF*(FF/2)];   // bf16 pairs along k
__device__ uint32_t g_Xhi[(size_t)PP*(FF/2)*QQ];   // [p][kp][q]
__device__ uint32_t g_Xlo[(size_t)PP*(FF/2)*QQ];
__device__ int   g_members[CC*TT];
__device__ int   g_cnt[CC];
__device__ float g_icnts[CC], g_sclS[CC], g_sclT[CC];

// ------------------------- bf16 split helper -------------------------
__device__ __forceinline__ void split2(float x0, float x1, uint32_t &hi, uint32_t &lo){
    __nv_bfloat16 h0 = __float2bfloat16(x0);
    __nv_bfloat16 h1 = __float2bfloat16(x1);
    float r0 = x0 - __bfloat162float(h0);
    float r1 = x1 - __bfloat162float(h1);
    __nv_bfloat16 l0 = __float2bfloat16(r0);
    __nv_bfloat16 l1 = __float2bfloat16(r1);
    hi = (uint32_t)__bfloat16_as_ushort(h0) | ((uint32_t)__bfloat16_as_ushort(h1) << 16);
    lo = (uint32_t)__bfloat16_as_ushort(l0) | ((uint32_t)__bfloat16_as_ushort(l1) << 16);
}
__device__ __forceinline__ uint32_t pack_hi2(float x0, float x1){
    __nv_bfloat16 h0 = __float2bfloat16(x0);
    __nv_bfloat16 h1 = __float2bfloat16(x1);
    return (uint32_t)__bfloat16_as_ushort(h0) | ((uint32_t)__bfloat16_as_ushort(h1) << 16);
}

#define MMA_BF16(c, a0,a1,a2,a3, b0,b1) \
    asm volatile("mma.sync.aligned.m16n8k16.row.col.f32.bf16.bf16.f32 " \
        "{%0,%1,%2,%3},{%4,%5,%6,%7},{%8,%9},{%0,%1,%2,%3};" \
        : "+f"(c[0]),"+f"(c[1]),"+f"(c[2]),"+f"(c[3]) \
        : "r"(a0),"r"(a1),"r"(a2),"r"(a3),"r"(b0),"r"(b1))

__device__ __forceinline__ void ldm4(uint32_t &r0, uint32_t &r1, uint32_t &r2, uint32_t &r3,
                                     uint32_t saddr){
    asm volatile("ldmatrix.sync.aligned.m8n8.x4.shared.b16 {%0,%1,%2,%3}, [%4];"
        : "=r"(r0), "=r"(r1), "=r"(r2), "=r"(r3) : "r"(saddr));
}
__device__ __forceinline__ uint32_t smem_u32(const void* p){
    uint32_t a;
    asm("{ .reg .u64 t; cvta.to.shared.u64 t, %1; cvt.u32.u64 %0, t; }" : "=r"(a) : "l"(p));
    return a;
}

// ------------------------- setup -------------------------
__global__ void setup_k(const int* __restrict__ lab_raw){
    if (threadIdx.x == 0 && blockIdx.x == 0){
        bool odd_all_zero = true;
        for (int t = 1; t < 200; t += 2) if (lab_raw[t] != 0) odd_all_zero = false;
        bool even_has_big = false;
        for (int t = 0; t < 200; t += 2) if (lab_raw[t] > 0) even_has_big = true;
        bool is64 = odd_all_zero && even_has_big;

        int cnt[CC];
        #pragma unroll
        for (int c = 0; c < CC; c++) cnt[c] = 0;
        for (int t = 0; t < TT; t++){
            int cc = is64 ? lab_raw[2*t] : lab_raw[t];
            if (cc < 0) cc = 0; if (cc >= CC) cc = CC-1;
            g_members[cc*TT + cnt[cc]] = t;
            cnt[cc]++;
        }
        for (int c = 0; c < CC; c++){
            g_cnt[c] = cnt[c];
            float cs  = fmaxf((float)cnt[c], 1.0f);
            g_icnts[c] = 1.0f / cs;
            float lam = cs / (cs + 1.0f);
            g_sclS[c] = lam / fmaxf((float)cnt[c] - 1.0f, 1.0f);
            g_sclT[c] = 1.0f - lam;
        }
    }
}

// ------------------------- class means -------------------------
__global__ void means_k(const float* __restrict__ sf){
    int pc = blockIdx.x;
    int p = pc / CC, c = pc % CC;
    int n = g_cnt[c];
    float ic = g_icnts[c];
    for (int f = threadIdx.x; f < FF; f += blockDim.x){
        float s = 0.0f;
        for (int m = 0; m < n; m++){
            int t = g_members[c*TT + m];
            s += sf[((size_t)p*TT + t)*FF + f];
        }
        g_means[(size_t)pc*FF + f] = s * ic;
    }
}

// ------------------------- task mean -------------------------
__global__ void tm_k(const float* __restrict__ sf){
    int p = blockIdx.x;
    for (int f = threadIdx.x; f < FF; f += blockDim.x){
        float s = 0.0f;
        for (int t = 0; t < TT; t++) s += sf[((size_t)p*TT + t)*FF + f];
        g_tm[p*FF + f] = s * (1.0f/TT);
    }
}

// ------------------------- task covariance -------------------------
__global__ void taskcov_k(const float* __restrict__ sf){
    int tile = blockIdx.x;          // 0..35 (tg<=tf)
    int p    = blockIdx.y;
    int tf = 0, rem = tile;
    while (rem >= tf+1){ rem -= tf+1; tf++; }
    int tg = rem;
    __shared__ float af[8][68], ag[8][68];
    int tid = threadIdx.x, tx = tid & 15, ty = tid >> 4;
    int r0 = ty*4, c0 = tx*4;
    float acc[4][4] = {};
    const float* tmv = g_tm + p*FF;
    for (int t0 = 0; t0 < TT; t0 += 8){
        __syncthreads();
        #pragma unroll
        for (int ii = 0; ii < 2; ii++){
            int idx = ii*256 + tid;
            int s = idx >> 6, f = idx & 63;
            const float* row = sf + ((size_t)p*TT + t0 + s)*FF;
            af[s][f] = row[tf*64 + f] - tmv[tf*64 + f];
            ag[s][f] = row[tg*64 + f] - tmv[tg*64 + f];
        }
        __syncthreads();
        #pragma unroll
        for (int s = 0; s < 8; s++){
            float a[4], b[4];
            #pragma unroll
            for (int i = 0; i < 4; i++) a[i] = af[s][r0+i];
            #pragma unroll
            for (int j = 0; j < 4; j++) b[j] = ag[s][c0+j];
            #pragma unroll
            for (int i = 0; i < 4; i++)
                #pragma unroll
                for (int j = 0; j < 4; j++) acc[i][j] += a[i]*b[j];
        }
    }
    const float inv = 1.0f/(TT-1);
    float* dst = g_task + (size_t)p*FF*FF;
    #pragma unroll
    for (int i = 0; i < 4; i++)
        #pragma unroll
        for (int j = 0; j < 4; j++){
            int fr = tf*64 + r0 + i, gc = tg*64 + c0 + j;
            float v = acc[i][j]*inv;
            dst[(size_t)fr*FF + gc] = v;
            dst[(size_t)gc*FF + fr] = v;
        }
}

// ------------------------- cov_reg -------------------------
__global__ void buildM_k(const float* __restrict__ sf){
    int tile = blockIdx.x;          // 0..35
    int pc   = blockIdx.y;
    int p = pc / CC, c = pc % CC;
    int tf = 0, rem = tile;
    while (rem >= tf+1){ rem -= tf+1; tf++; }
    int tg = rem;
    __shared__ float af[4][68], ag[4][68];
    int tid = threadIdx.x, tx = tid & 15, ty = tid >> 4;
    int r0 = ty*4, c0 = tx*4;
    float acc[4][4] = {};
    int n = g_cnt[c];
    const float* mu = g_means + (size_t)pc*FF;
    for (int m0 = 0; m0 < n; m0 += 4){
        __syncthreads();
        {
            int s = tid >> 6, f = tid & 63;
            int m = m0 + s;
            float va = 0.0f, vg = 0.0f;
            if (m < n){
                int t = g_members[c*TT + m];
                const float* row = sf + ((size_t)p*TT + t)*FF;
                va = row[tf*64 + f] - mu[tf*64 + f];
                vg = row[tg*64 + f] - mu[tg*64 + f];
            }
            af[s][f] = va; ag[s][f] = vg;
        }
        __syncthreads();
        #pragma unroll
        for (int s = 0; s < 4; s++){
            float a[4], b[4];
            #pragma unroll
            for (int i = 0; i < 4; i++) a[i] = af[s][r0+i];
            #pragma unroll
            for (int j = 0; j < 4; j++) b[j] = ag[s][c0+j];
            #pragma unroll
            for (int i = 0; i < 4; i++)
                #pragma unroll
                for (int j = 0; j < 4; j++) acc[i][j] += a[i]*b[j];
        }
    }
    float ss = g_sclS[c], st = g_sclT[c];
    float* dst = g_M + (size_t)pc*FF*FF;
    const float* tk = g_task + (size_t)p*FF*FF;
    #pragma unroll
    for (int i = 0; i < 4; i++)
        #pragma unroll
        for (int j = 0; j < 4; j++){
            int fr = tf*64 + r0 + i, gc = tg*64 + c0 + j;
            float v = ss*acc[i][j] + st*tk[(size_t)fr*FF + gc] + ((fr == gc) ? 1.0f : 0.0f);
            dst[(size_t)fr*FF + gc] = v;
            dst[(size_t)gc*FF + fr] = v;
        }
}

// -------- zero Whi in the upper-right 64x64 of each 128-diag block --------
__global__ void zeroWu_k(){
    int rb  = blockIdx.x;
    int mat = blockIdx.y;
    uint32_t* wh = g_Whi + (size_t)mat*FF*(FF/2);
    for (int e = threadIdx.x; e < 64*32; e += 256){
        int r = e >> 5, cp = e & 31;
        size_t o = (size_t)(rb*128 + r)*(FF/2) + rb*64 + 32 + cp;
        wh[o] = 0u;
    }
}

// -------- zero g_quad --------
__global__ void zeroquad_k(){
    size_t n = (size_t)PP*QQ*CC;
    for (size_t i = (size_t)blockIdx.x*blockDim.x + threadIdx.x; i < n;
         i += (size_t)gridDim.x*blockDim.x)
        g_quad[i] = 0.0f;
}

// ------------- 64x64 float4 tile helpers (pitch 17 float4 = 68 words) -------------
#define PTW 68
#define PT4 17
__device__ __forceinline__ void ldt4(float4* dst, const float* g, int tid){
    #pragma unroll
    for (int e = tid; e < 1024; e += 256){
        int r = e >> 4, c4 = e & 15;
        dst[r*PT4 + c4] = *(const float4*)&g[(size_t)r*FF + c4*4];
    }
}
__device__ __forceinline__ float dot4(float4 a, float4 b){
    return a.x*b.x + a.y*b.y + a.z*b.z + a.w*b.w;
}
// C[r][c] += A[r][k]*B[c][k]; rows ty*4+i, cols tx+16*j
__device__ __forceinline__ void g64_nt4(const float4* A, const float4* B,
                                        float acc[4][4], int ty, int tx){
    #pragma unroll 4
    for (int kq = 0; kq < 16; kq++){
        float4 a[4], b[4];
        #pragma unroll
        for (int i = 0; i < 4; i++) a[i] = A[(ty*4+i)*PT4 + kq];
        #pragma unroll
        for (int j = 0; j < 4; j++) b[j] = B[(tx+16*j)*PT4 + kq];
        #pragma unroll
        for (int i = 0; i < 4; i++)
            #pragma unroll
            for (int j = 0; j < 4; j++) acc[i][j] += dot4(a[i], b[j]);
    }
}
// C[r][c] += A[r][k]*B[k][c]; rows ty*4+i, cols 4*tx+j
__device__ __forceinline__ void g64_nn4(const float4* A, const float4* B,
                                        float acc[4][4], int ty, int tx){
    #pragma unroll 2
    for (int kq = 0; kq < 16; kq++){
        float4 a[4];
        #pragma unroll
        for (int i = 0; i < 4; i++) a[i] = A[(ty*4+i)*PT4 + kq];
        #pragma unroll
        for (int kk = 0; kk < 4; kk++){
            float4 b = B[(4*kq+kk)*PT4 + tx];
            float av[4];
            #pragma unroll
            for (int i = 0; i < 4; i++)
                av[i] = (kk == 0) ? a[i].x : (kk == 1) ? a[i].y : (kk == 2) ? a[i].z : a[i].w;
            #pragma unroll
            for (int i = 0; i < 4; i++){
                acc[i][0] += av[i]*b.x;
                acc[i][1] += av[i]*b.y;
                acc[i][2] += av[i]*b.z;
                acc[i][3] += av[i]*b.w;
            }
        }
    }
}

// -------------- Phase A step j: diag factor + tri-inverse + panel --------
__global__ void __launch_bounds__(256) diagpanel_k(int j){
    extern __shared__ float sm[];
    float* sA = sm;                 // 64*68 words
    float* sB = sm + 64*PTW;
    float* sC = sm + 2*64*PTW;
    float4* sA4 = (float4*)sA;
    float4* sB4 = (float4*)sB;
    float4* sC4 = (float4*)sC;
    int mat = blockIdx.x;
    float* M = g_M + (size_t)mat*FF*FF;
    float* W = g_W + (size_t)mat*FF*FF;
    int tid = threadIdx.x, tx = tid & 15, ty = tid >> 4;

    ldt4(sA4, M + (size_t)(j*64)*FF + j*64, tid);
    __syncthreads();
    // LDL^T elimination (1 barrier per column)
    for (int k = 0; k < 64; k++){
        float pinv = 1.0f / sA[k*PTW+k];
        #pragma unroll 4
        for (int e = tid; e < 4096; e += 256){
            int r = e >> 6, cc = e & 63;
            if (r > k && cc > k && cc <= r)
                sA[r*PTW+cc] -= sA[r*PTW+k]*sA[cc*PTW+k]*pinv;
        }
        __syncthreads();
    }
    if (tid < 64) sC[tid] = rsqrtf(sA[tid*PTW+tid]);
    __syncthreads();
    #pragma unroll 4
    for (int e = tid; e < 4096; e += 256){
        int r = e >> 6, cc = e & 63;
        if (cc <= r) sA[r*PTW+cc] *= sC[cc];
    }
    __syncthreads();

    // triangular inverse of L_jj -> sB (4 lanes per column)
    #pragma unroll 4
    for (int e = tid; e < 4096; e += 256) sB[(e>>6)*PTW + (e&63)] = 0.0f;
    __syncthreads();
    {
        int c = tid >> 2, s = tid & 3;
        unsigned gmask = 0xFu << ((tid & 31) & ~3);
        float dv = 1.0f / sA[c*PTW+c];
        if (s == 0) sB[c*PTW+c] = dv;
        __syncwarp(gmask);
        for (int r = c+1; r < 64; r++){
            float part = 0.0f;
            for (int k2 = c + s; k2 < r; k2 += 4)
                part += sA[r*PTW+k2] * sB[k2*PTW+c];
            part += __shfl_xor_sync(gmask, part, 1);
            part += __shfl_xor_sync(gmask, part, 2);
            if (s == 0) sB[r*PTW+c] = -part / sA[r*PTW+r];
            __syncwarp(gmask);
        }
    }
    __syncthreads();
    // store Linv_jj into W (fp32) + bf16 hi split
    #pragma unroll 4
    for (int e = tid; e < 4096; e += 256){
        int r = e >> 6, cc = e & 63;
        W[(size_t)(j*64 + r)*FF + j*64 + cc] = sB[r*PTW+cc];
    }
    {
        uint32_t* wh = g_Whi + (size_t)mat*FF*(FF/2);
        for (int e = tid; e < 2048; e += 256){
            int r = e >> 5, cp = e & 31;
            size_t o = (size_t)(j*64 + r)*(FF/2) + j*32 + cp;
            wh[o] = pack_hi2(sB[r*PTW + 2*cp], sB[r*PTW + 2*cp + 1]);
        }
    }
    // panel: L_ij = A_ij * Linv_jj^T (NT, cols tx+16*j2)
    for (int i = j+1; i < 8; i++){
        __syncthreads();
        ldt4(sC4, M + (size_t)(i*64)*FF + j*64, tid);
        __syncthreads();
        float acc[4][4] = {};
        g64_nt4(sC4, sB4, acc, ty, tx);
        #pragma unroll
        for (int ii = 0; ii < 4; ii++)
            #pragma unroll
            for (int j2 = 0; j2 < 4; j2++)
                M[(size_t)(i*64 + ty*4 + ii)*FF + j*64 + tx + 16*j2] = acc[ii][j2];
    }
}

// -------------- Phase A trailing -------------
__global__ void __launch_bounds__(256) trailing_k(int j){
    extern __shared__ float sm[];
    float4* sA4 = (float4*)sm;
    float4* sB4 = (float4*)(sm + 64*PTW);
    int mat = blockIdx.y;
    int t = blockIdx.x;
    int i = j+1, cnt = 1;
    while (t >= cnt){ t -= cnt; i++; cnt = i - j; }
    int kk = j+1 + t;
    float* M = g_M + (size_t)mat*FF*FF;
    int tid = threadIdx.x, tx = tid & 15, ty = tid >> 4;
    ldt4(sA4, M + (size_t)(i*64)*FF + j*64, tid);
    ldt4(sB4, M + (size_t)(kk*64)*FF + j*64, tid);
    __syncthreads();
    float acc[4][4] = {};
    g64_nt4(sA4, sB4, acc, ty, tx);
    #pragma unroll
    for (int ii = 0; ii < 4; ii++)
        #pragma unroll
        for (int j2 = 0; j2 < 4; j2++){
            size_t o = (size_t)(i*64 + ty*4 + ii)*FF + kk*64 + tx + 16*j2;
            M[o] -= acc[ii][j2];
        }
}

// -------------- Phase B (writes W fp32 + bf16 hi split) -------------
__global__ void __launch_bounds__(256) phaseB_k(){
    extern __shared__ float sm[];
    float* sA = sm;
    float* sC = sm + 2*64*PTW;
    float4* sA4 = (float4*)sA;
    float4* sB4 = (float4*)(sm + 64*PTW);
    float4* sC4 = (float4*)sC;
    int j   = blockIdx.x;
    int mat = blockIdx.y;
    float* M = g_M + (size_t)mat*FF*FF;
    float* W = g_W + (size_t)mat*FF*FF;
    uint32_t* wh = g_Whi + (size_t)mat*FF*(FF/2);
    int tid = threadIdx.x, tx = tid & 15, ty = tid >> 4;

    for (int i = j+1; i < 8; i++){
        float acc[4][4] = {};
        for (int k = j; k < i; k++){
            __syncthreads();
            ldt4(sA4, M + (size_t)(i*64)*FF + k*64, tid);
            ldt4(sB4, W + (size_t)(k*64)*FF + j*64, tid);
            __syncthreads();
            g64_nn4(sA4, sB4, acc, ty, tx);
        }
        __syncthreads();
        #pragma unroll
        for (int ii = 0; ii < 4; ii++){
            float4 v = {acc[ii][0], acc[ii][1], acc[ii][2], acc[ii][3]};
            sC4[(ty*4 + ii)*PT4 + tx] = v;
        }
        ldt4(sA4, W + (size_t)(i*64)*FF + i*64, tid);
        __syncthreads();
        float acc2[4][4] = {};
        g64_nn4(sA4, sC4, acc2, ty, tx);
        #pragma unroll
        for (int ii = 0; ii < 4; ii++){
            float v0 = -acc2[ii][0], v1 = -acc2[ii][1], v2 = -acc2[ii][2], v3 = -acc2[ii][3];
            float4 v = {v0, v1, v2, v3};
            size_t row = (size_t)(i*64 + ty*4 + ii);
            *(float4*)&W[row*FF + j*64 + 4*tx] = v;
            size_t o = row*(FF/2) + j*32 + 2*tx;
            wh[o]   = pack_hi2(v0, v1);
            wh[o+1] = pack_hi2(v2, v3);
        }
        __syncthreads();
    }
}

// ------------------------- queries split + transpose: [p][kp][q] -------------------------
__global__ void qsplit_k(const float* __restrict__ qf){
    __shared__ float sq[16][FF];
    int qb = blockIdx.x;           // 0..63 (16 queries each)
    int p  = blockIdx.y;
    int tid = threadIdx.x;
    for (int u = tid; u < 16*FF; u += 256){
        int qi = u / FF, f = u % FF;
        sq[qi][f] = qf[((size_t)p*QQ + qb*16 + qi)*FF + f];
    }
    __syncthreads();
    uint32_t* dh = g_Xhi + (size_t)p*(FF/2)*QQ;
    uint32_t* dl = g_Xlo + (size_t)p*(FF/2)*QQ;
    for (int u = tid; u < 256*16; u += 256){
        int kp = u >> 4, qi = u & 15;
        uint32_t hi, lo;
        split2(sq[qi][2*kp], sq[qi][2*kp+1], hi, lo);
        dh[(size_t)kp*QQ + qb*16 + qi] = hi;
        dl[(size_t)kp*QQ + qb*16 + qi] = lo;
    }
}

// ------------------------- y = W * mu (fp32 exact, triangular) -------------------------
__global__ void ymu_k(){
    __shared__ float smu[FF];
    int pc = blockIdx.x;
    int tid = threadIdx.x, lane = tid & 31, wid = tid >> 5;
    const float* W = g_W + (size_t)pc*FF*FF;
    for (int f = tid; f < FF; f += 256) smu[f] = g_means[(size_t)pc*FF + f];
    __syncthreads();
    for (int r = wid; r < FF; r += 8){
        float s = 0.0f;
        for (int k = lane; k <= r; k += 32)
            s += W[(size_t)r*FF + k] * smu[k];
        #pragma unroll
        for (int o = 16; o; o >>= 1) s += __shfl_xor_sync(0xFFFFFFFFu, s, o);
        if (lane == 0) g_Ymu[pc*FF + r] = s;
    }
}

// ================= quad via mma.sync (2-term): quad = || y - bf16(W) x ||^2 =================
// Grid (8 qtiles, 160 pc, 4 rb), 256 threads (8 warps: 2 m x 4 n), 2 CTAs/SM.
#define WPITCH 36
#define XPITCH 136
#define QMMA_SMEM (128*WPITCH*4 + 2*32*XPITCH*4 + 128*4)
__global__ void __launch_bounds__(256, 2) quadmma_k(){
    extern __shared__ uint32_t smu32[];
    uint32_t* sWhi = smu32;
    uint32_t* sXhi = sWhi + 128*WPITCH;
    uint32_t* sXlo = sXhi + 32*XPITCH;
    float*    red  = (float*)(sXlo + 32*XPITCH);
    int pc = blockIdx.y;
    int p = pc / CC, c = pc % CC;
    int qbase = blockIdx.x * 128;
    int rb = blockIdx.z;
    int tid = threadIdx.x, lane = tid & 31, wid = tid >> 5;
    int g = lane >> 2, t = lane & 3;
    int warpM = wid & 1, warpN = wid >> 1;
    int lm_row = (lane & 7) + ((lane >> 3) & 1)*8;
    int lm_col = (lane >> 4)*4;
    uint32_t sWhi_b = smem_u32(sWhi);
    const uint4* gwh4 = (const uint4*)(g_Whi + (size_t)pc*FF*(FF/2));
    const uint4* gxh4 = (const uint4*)(g_Xhi + (size_t)p*(FF/2)*QQ + qbase);
    const uint4* gxl4 = (const uint4*)(g_Xlo + (size_t)p*(FF/2)*QQ + qbase);
    const float* ym = g_Ymu + pc*FF;

    if (tid < 128) red[tid] = 0.0f;
    float qs[8];
    #pragma unroll
    for (int j = 0; j < 8; j++) qs[j] = 0.0f;

    float acc[4][4][4];
    #pragma unroll
    for (int mi = 0; mi < 4; mi++)
        #pragma unroll
        for (int ni = 0; ni < 4; ni++)
            #pragma unroll
            for (int r = 0; r < 4; r++) acc[mi][ni][r] = 0.0f;

    int nch = 2*rb + 2;
    for (int ch = 0; ch < nch; ch++){
        int kp0 = ch*32;
        __syncthreads();
        // stage W hi (uint4): row r, 8 uint4 across 32 kp
        #pragma unroll
        for (int u = tid; u < 1024; u += 256){
            int r = u >> 3, c4 = u & 7;
            size_t go = (size_t)(rb*128 + r)*(FF/8) + (kp0 >> 2) + c4;
            *(uint4*)&sWhi[r*WPITCH + c4*4] = gwh4[go];
        }
        // stage X hi/lo (uint4): row kp, 32 uint4 across 128 q
        #pragma unroll
        for (int u = tid; u < 1024; u += 256){
            int kp = u >> 5, q4 = u & 31;
            size_t go = (size_t)(kp0 + kp)*(QQ/4) + q4;
            *(uint4*)&sXhi[kp*XPITCH + q4*4] = gxh4[go];
            *(uint4*)&sXlo[kp*XPITCH + q4*4] = gxl4[go];
        }
        __syncthreads();
        bool diag = (ch >= 2*rb);
        int kbase = (ch - 2*rb)*64;
        #pragma unroll
        for (int s = 0; s < 4; s++){
            uint32_t bh[4][2], bl[4][2];
            #pragma unroll
            for (int ni = 0; ni < 4; ni++){
                int col = warpN*32 + ni*8 + g;
                bh[ni][0] = sXhi[(8*s + t)*XPITCH + col];
                bh[ni][1] = sXhi[(8*s + t + 4)*XPITCH + col];
                bl[ni][0] = sXlo[(8*s + t)*XPITCH + col];
                bl[ni][1] = sXlo[(8*s + t + 4)*XPITCH + col];
            }
            #pragma unroll
            for (int mi = 0; mi < 4; mi++){
                if (diag && (warpM*64 + mi*16 + 16 <= kbase + 16*s)) continue;
                uint32_t off = (uint32_t)(((warpM*64 + mi*16 + lm_row)*WPITCH + 8*s + lm_col)*4);
                uint32_t ah0,ah1,ah2,ah3;
                ldm4(ah0,ah1,ah2,ah3, sWhi_b + off);
                #pragma unroll
                for (int ni = 0; ni < 4; ni++){
                    MMA_BF16(acc[mi][ni], ah0,ah1,ah2,ah3, bh[ni][0],bh[ni][1]);
                    MMA_BF16(acc[mi][ni], ah0,ah1,ah2,ah3, bl[ni][0],bl[ni][1]);
                }
            }
        }
    }
    // epilogue: qs += (y - z)^2 over this CTA's 128 rows
    #pragma unroll
    for (int mi = 0; mi < 4; mi++){
        int r1 = rb*128 + warpM*64 + mi*16 + g;
        float y1 = ym[r1], y2 = ym[r1 + 8];
        #pragma unroll
        for (int ni = 0; ni < 4; ni++){
            float d0 = y1 - acc[mi][ni][0];
            float d1 = y1 - acc[mi][ni][1];
            float d2 = y2 - acc[mi][ni][2];
            float d3 = y2 - acc[mi][ni][3];
            qs[2*ni]   += d0*d0 + d2*d2;
            qs[2*ni+1] += d1*d1 + d3*d3;
        }
    }

    #pragma unroll
    for (int j = 0; j < 8; j++)
        #pragma unroll
        for (int o = 4; o < 32; o <<= 1)
            qs[j] += __shfl_xor_sync(0xFFFFFFFFu, qs[j], o);
    if (lane < 4){
        #pragma unroll
        for (int j = 0; j < 8; j++){
            int ni = j >> 1, b = j & 1;
            int q = warpN*32 + ni*8 + 2*lane + b;
            atomicAdd(&red[q], qs[j]);
        }
    }
    __syncthreads();
    if (tid < 128)
        atomicAdd(&g_quad[((size_t)p*QQ + qbase + tid)*CC + c], red[tid]);
}

// ------------------------- final outputs -------------------------
__global__ void logits_k(float* out){
    int q = blockIdx.x;
    int c = threadIdx.x;
    if (c < CC){
        float s = 0.0f;
        #pragma unroll
        for (int p = 0; p < PP; p++) s += g_quad[((size_t)p*QQ + q)*CC + c];
        out[q*CC + c] = -s * (1.0f/PP);
    }
}
__global__ void copymeans_k(float* out){
    for (int i = blockIdx.x*blockDim.x + threadIdx.x; i < NM*FF; i += gridDim.x*blockDim.x)
        out[QQ*CC + i] = g_means[i];
}

// ------------------------- launch -------------------------
extern "C" void kernel_launch(void* const* d_in, const int* in_sizes, int n_in,
                              void* d_out, int out_size) {
    const float* sf  = (const float*)d_in[0];
    const int*   lab = (const int*)d_in[1];
    const float* qf  = (const float*)d_in[2];
    float* out = (float*)d_out;

    const int CHOL_SMEM = 3*64*PTW*(int)sizeof(float);   // 52224
    const int TR_SMEM   = 2*64*PTW*(int)sizeof(float);   // 34816
    cudaFuncSetAttribute(diagpanel_k, cudaFuncAttributeMaxDynamicSharedMemorySize, CHOL_SMEM);
    cudaFuncSetAttribute(phaseB_k,    cudaFuncAttributeMaxDynamicSharedMemorySize, CHOL_SMEM);
    cudaFuncSetAttribute(quadmma_k,   cudaFuncAttributeMaxDynamicSharedMemorySize, QMMA_SMEM);

    setup_k<<<1, 32>>>(lab);
    means_k<<<NM, 256>>>(sf);
    tm_k<<<PP, 256>>>(sf);
    qsplit_k<<<dim3(64, PP), 256>>>(qf);
    taskcov_k<<<dim3(36, PP), 256>>>(sf);
    buildM_k<<<dim3(36, NM), 256>>>(sf);
    zeroWu_k<<<dim3(4, NM), 256>>>();
    zeroquad_k<<<160, 256>>>();
    for (int j = 0; j < 8; j++){
        diagpanel_k<<<NM, 256, CHOL_SMEM>>>(j);
        int nt = (7-j)*(8-j)/2;
        if (nt > 0)
            trailing_k<<<dim3(nt, NM), 256, TR_SMEM>>>(j);
    }
    phaseB_k<<<dim3(7, NM), 256, CHOL_SMEM>>>();
    ymu_k<<<NM, 256>>>();
    quadmma_k<<<dim3(8, NM, 4), 256, QMMA_SMEM>>>();
    logits_k<<<QQ, 32>>>(out);
    if (out_size >= QQ*CC + NM*FF)
        copymeans_k<<<160, 512>>>(out);
}